// round 1
// baseline (speedup 1.0000x reference)
#include <cuda_runtime.h>
#include <math.h>
#include <stdint.h>

// ---------------------------------------------------------------------------
// Problem constants (fixed by the reference)
// ---------------------------------------------------------------------------
constexpr int kB     = 16;
constexpr int kH     = 32;
constexpr int kW     = 32;
constexpr int kC     = 384;
constexpr int kDI    = 768;      // 2*C
constexpr int kDTR   = 24;
constexpr int kHID   = 1536;     // 4*C
constexpr int kL     = kH * kW;          // 1024
constexpr int kNTOK  = kB * kL;          // 16384
constexpr int kXPK   = kDTR + 2;         // 26 (dt_rank + B + C)

// ---------------------------------------------------------------------------
// Scratch (static device globals — no allocations allowed)
// ---------------------------------------------------------------------------
__device__ float g_h1  [(size_t)kNTOK * kC];
__device__ float g_xz  [(size_t)kNTOK * 2 * kDI];
__device__ float g_u   [(size_t)kNTOK * kDI];
__device__ float g_dtbc[(size_t)kNTOK * kXPK];
__device__ float g_a   [(size_t)kNTOK * kDI];
__device__ float g_bu  [(size_t)kNTOK * kDI];
__device__ float g_y   [(size_t)kNTOK * kDI];
__device__ float g_gate[(size_t)kNTOK * kDI];
__device__ float g_xres[(size_t)kNTOK * kC];
__device__ float g_h2  [(size_t)kNTOK * kC];
__device__ float g_hid [(size_t)kNTOK * kHID];

// ---------------------------------------------------------------------------
// Math helpers
// ---------------------------------------------------------------------------
__device__ __forceinline__ float siluf(float x) {
    return x / (1.f + expf(-x));
}
__device__ __forceinline__ float softplusf(float x) {
    // jnp.logaddexp(x, 0) = max(x,0) + log1p(exp(-|x|))
    return fmaxf(x, 0.f) + log1pf(expf(-fabsf(x)));
}
__device__ __forceinline__ float gelu_tanh(float x) {
    float x3 = x * x * x;
    return 0.5f * x * (1.f + tanhf(0.7978845608028654f * (x + 0.044715f * x3)));
}

// ---------------------------------------------------------------------------
// LayerNorm (optionally fused with * silu(z))
//   CH channels per row, TPB threads, PER = CH/TPB elements per thread.
// ---------------------------------------------------------------------------
template <int CH, int TPB, bool MUL_SILU>
__global__ __launch_bounds__(TPB) void ln_kernel(
    const float* __restrict__ in,
    const float* __restrict__ zsrc, int zld, int zoff,
    const float* __restrict__ gam, const float* __restrict__ bet,
    float* __restrict__ out, float eps)
{
    constexpr int PER = CH / TPB;
    const int n = blockIdx.x;
    const float* row = in + (size_t)n * CH;

    float v[PER];
    float s = 0.f, s2 = 0.f;
#pragma unroll
    for (int i = 0; i < PER; i++) {
        float t = row[i * TPB + threadIdx.x];
        v[i] = t; s += t; s2 += t * t;
    }
    __shared__ float sm[2 * (TPB / 32)];
#pragma unroll
    for (int o = 16; o; o >>= 1) {
        s  += __shfl_down_sync(0xffffffffu, s,  o);
        s2 += __shfl_down_sync(0xffffffffu, s2, o);
    }
    const int wid = threadIdx.x >> 5, lid = threadIdx.x & 31;
    if (lid == 0) { sm[wid] = s; sm[TPB / 32 + wid] = s2; }
    __syncthreads();
    if (threadIdx.x == 0) {
        float a = 0.f, b = 0.f;
#pragma unroll
        for (int i = 0; i < TPB / 32; i++) { a += sm[i]; b += sm[TPB / 32 + i]; }
        sm[0] = a; sm[1] = b;
    }
    __syncthreads();
    const float mu  = sm[0] * (1.f / CH);
    const float var = sm[1] * (1.f / CH) - mu * mu;
    const float inv = rsqrtf(var + eps);
#pragma unroll
    for (int i = 0; i < PER; i++) {
        const int c = i * TPB + threadIdx.x;
        float o = (v[i] - mu) * inv * gam[c] + bet[c];
        if (MUL_SILU) {
            float z = zsrc[(size_t)n * zld + zoff + c];
            o *= siluf(z);
        }
        out[(size_t)n * CH + c] = o;
    }
}

// ---------------------------------------------------------------------------
// SGEMM 128x128x8, 8x8 microtile, 256 threads. C = A(MxK) @ B(KxN) [+ epilogue]
// EPI: 0=store  1=+resid  2=+bias->gelu  3=+bias+resid
// Requires M%128==0, N%128==0, K%8==0.
// ---------------------------------------------------------------------------
template <int EPI>
__global__ __launch_bounds__(256) void sgemm_kernel(
    const float* __restrict__ A, const float* __restrict__ B,
    float* __restrict__ Cmat, int M, int N, int K,
    const float* __restrict__ bias, const float* __restrict__ resid)
{
    constexpr int BM = 128, BN = 128, BK = 8, TM = 8, TN = 8;
    __shared__ float As[BK][BM];
    __shared__ float Bs[BK][BN];

    const int tid  = threadIdx.x;
    const int trow = tid / 16, tcol = tid % 16;
    const int by = blockIdx.y, bx = blockIdx.x;

    const float* Ap = A + (size_t)by * BM * K;
    const float* Bp = B + (size_t)bx * BN;

    const int aRow = tid >> 1,   aCol = (tid & 1) * 4;
    const int bRow = tid >> 5,   bCol = (tid & 31) * 4;

    float acc[TM][TN];
#pragma unroll
    for (int i = 0; i < TM; i++)
#pragma unroll
        for (int j = 0; j < TN; j++) acc[i][j] = 0.f;

    for (int k0 = 0; k0 < K; k0 += BK) {
        float4 av = *reinterpret_cast<const float4*>(Ap + (size_t)aRow * K + k0 + aCol);
        As[aCol + 0][aRow] = av.x;
        As[aCol + 1][aRow] = av.y;
        As[aCol + 2][aRow] = av.z;
        As[aCol + 3][aRow] = av.w;
        float4 bv = *reinterpret_cast<const float4*>(Bp + (size_t)(k0 + bRow) * N + bCol);
        *reinterpret_cast<float4*>(&Bs[bRow][bCol]) = bv;
        __syncthreads();
#pragma unroll
        for (int k = 0; k < BK; k++) {
            float rm[TM], rn[TN];
            *reinterpret_cast<float4*>(rm)     = *reinterpret_cast<const float4*>(&As[k][trow * TM]);
            *reinterpret_cast<float4*>(rm + 4) = *reinterpret_cast<const float4*>(&As[k][trow * TM + 4]);
            *reinterpret_cast<float4*>(rn)     = *reinterpret_cast<const float4*>(&Bs[k][tcol * TN]);
            *reinterpret_cast<float4*>(rn + 4) = *reinterpret_cast<const float4*>(&Bs[k][tcol * TN + 4]);
#pragma unroll
            for (int i = 0; i < TM; i++)
#pragma unroll
                for (int j = 0; j < TN; j++)
                    acc[i][j] = fmaf(rm[i], rn[j], acc[i][j]);
        }
        __syncthreads();
    }

#pragma unroll
    for (int i = 0; i < TM; i++) {
        const int row = by * BM + trow * TM + i;
#pragma unroll
        for (int j = 0; j < TN; j++) {
            const int col = bx * BN + tcol * TN + j;
            float v = acc[i][j];
            if (EPI == 1) v += resid[(size_t)row * N + col];
            if (EPI == 2) v = gelu_tanh(v + bias[col]);
            if (EPI == 3) v += bias[col] + resid[(size_t)row * N + col];
            Cmat[(size_t)row * N + col] = v;
        }
    }
}

// ---------------------------------------------------------------------------
// Depthwise 3x3 SAME conv on channels-last tokens + silu.
// Input: xm = xz[:, 0:DI] (row stride 2*DI). Output: u (NTOK x DI).
// ---------------------------------------------------------------------------
__global__ void conv_silu_kernel(const float* __restrict__ xz,
                                 const float* __restrict__ cw,
                                 float* __restrict__ u)
{
    const int idx = blockIdx.x * blockDim.x + threadIdx.x;
    if (idx >= kNTOK * kDI) return;
    const int d = idx % kDI;
    const int n = idx / kDI;
    const int w = n % kW;
    const int h = (n / kW) % kH;

    float acc = 0.f;
#pragma unroll
    for (int ky = 0; ky < 3; ky++) {
        const int hh = h + ky - 1;
        if (hh < 0 || hh >= kH) continue;
#pragma unroll
        for (int kx = 0; kx < 3; kx++) {
            const int ww = w + kx - 1;
            if (ww < 0 || ww >= kW) continue;
            const int nn = n + (ky - 1) * kW + (kx - 1);
            acc = fmaf(cw[d * 9 + ky * 3 + kx],
                       xz[(size_t)nn * (2 * kDI) + d], acc);
        }
    }
    u[idx] = siluf(acc);
}

// ---------------------------------------------------------------------------
// x_proj: out[n,k] = sum_d u[n,d] * W[d,k], k in [0,26). Warp per token,
// 8 tokens per block; W staged through smem in 64-row chunks.
// ---------------------------------------------------------------------------
__global__ __launch_bounds__(256) void xproj_kernel(
    const float* __restrict__ u, const float* __restrict__ W,
    float* __restrict__ out)
{
    __shared__ float sW[64 * kXPK];
    const int warp = threadIdx.x >> 5, lane = threadIdx.x & 31;
    const int n = blockIdx.x * 8 + warp;
    float acc = 0.f;

    for (int j0 = 0; j0 < kDI; j0 += 64) {
        for (int i = threadIdx.x; i < 64 * kXPK; i += 256)
            sW[i] = W[j0 * kXPK + i];
        __syncthreads();

        const float uv0 = u[(size_t)n * kDI + j0 + lane];
        const float uv1 = u[(size_t)n * kDI + j0 + 32 + lane];
#pragma unroll
        for (int jj = 0; jj < 32; jj++) {
            const float uj = __shfl_sync(0xffffffffu, uv0, jj);
            if (lane < kXPK) acc = fmaf(uj, sW[jj * kXPK + lane], acc);
        }
#pragma unroll
        for (int jj = 0; jj < 32; jj++) {
            const float uj = __shfl_sync(0xffffffffu, uv1, jj);
            if (lane < kXPK) acc = fmaf(uj, sW[(32 + jj) * kXPK + lane], acc);
        }
        __syncthreads();
    }
    if (lane < kXPK) out[(size_t)n * kXPK + lane] = acc;
}

// ---------------------------------------------------------------------------
// dt_proj + softplus + precompute scan coefficients:
//   dt = softplus(dt_raw @ dtw + dtb);  a = exp(dt * A_d);  bu = dt * B * u
// ---------------------------------------------------------------------------
__global__ void dt_kernel(const float* __restrict__ dtbc,
                          const float* __restrict__ dtw,
                          const float* __restrict__ dtb,
                          const float* __restrict__ A_log,
                          const float* __restrict__ u,
                          float* __restrict__ a, float* __restrict__ bu)
{
    const int idx = blockIdx.x * blockDim.x + threadIdx.x;
    if (idx >= kNTOK * kDI) return;
    const int d = idx % kDI;
    const int n = idx / kDI;
    const float* r = dtbc + (size_t)n * kXPK;

    float acc = dtb[d];
#pragma unroll
    for (int j = 0; j < kDTR; j++)
        acc = fmaf(r[j], dtw[j * kDI + d], acc);

    const float dtv = softplusf(acc);
    const float Ad  = -expf(A_log[d]);
    a[idx]  = expf(dtv * Ad);
    bu[idx] = dtv * r[kDTR] * u[idx];   // r[24] = B coefficient
}

// ---------------------------------------------------------------------------
// Selective scan (DS=1): per (b,d) sequence over L:
//   h = a*h + bu;  y = h*Cc + u*D
// Thread per (b,d). Grid = 16 batches * 3 d-groups of 256.
// ---------------------------------------------------------------------------
__global__ __launch_bounds__(256) void scan_kernel(
    const float* __restrict__ a, const float* __restrict__ bu,
    const float* __restrict__ u, const float* __restrict__ dtbc,
    const float* __restrict__ Dp, float* __restrict__ y)
{
    const int b = blockIdx.x / 3;
    const int d = (blockIdx.x % 3) * 256 + threadIdx.x;
    const float Dd = Dp[d];
    float h = 0.f;
    const size_t base = (size_t)b * kL * kDI + d;
    const size_t cbase = (size_t)b * kL;
#pragma unroll 4
    for (int l = 0; l < kL; l++) {
        const size_t idx = base + (size_t)l * kDI;
        const float cc = __ldg(&dtbc[(cbase + l) * kXPK + (kDTR + 1)]);
        h = fmaf(a[idx], h, bu[idx]);
        y[idx] = fmaf(h, cc, u[idx] * Dd);
    }
}

// ---------------------------------------------------------------------------
// Launch
// ---------------------------------------------------------------------------
extern "C" void kernel_launch(void* const* d_in, const int* in_sizes, int n_in,
                              void* d_out, int out_size)
{
    const float* x         = (const float*)d_in[0];
    const float* ln1_g     = (const float*)d_in[1];
    const float* ln1_b     = (const float*)d_in[2];
    const float* w_in      = (const float*)d_in[3];
    const float* conv_w    = (const float*)d_in[4];
    const float* x_proj_w  = (const float*)d_in[5];
    const float* dt_proj_w = (const float*)d_in[6];
    const float* dt_proj_b = (const float*)d_in[7];
    const float* A_log     = (const float*)d_in[8];
    const float* Dp        = (const float*)d_in[9];
    const float* outnorm_g = (const float*)d_in[10];
    const float* outnorm_b = (const float*)d_in[11];
    const float* w_out     = (const float*)d_in[12];
    const float* ln2_g     = (const float*)d_in[13];
    const float* ln2_b     = (const float*)d_in[14];
    const float* fc1_w     = (const float*)d_in[15];
    const float* fc1_b     = (const float*)d_in[16];
    const float* fc2_w     = (const float*)d_in[17];
    const float* fc2_b     = (const float*)d_in[18];
    float* out = (float*)d_out;

    float *h1, *xz, *u, *dtbc, *a, *bu, *y, *gate, *xres, *h2, *hid;
    cudaGetSymbolAddress((void**)&h1,   g_h1);
    cudaGetSymbolAddress((void**)&xz,   g_xz);
    cudaGetSymbolAddress((void**)&u,    g_u);
    cudaGetSymbolAddress((void**)&dtbc, g_dtbc);
    cudaGetSymbolAddress((void**)&a,    g_a);
    cudaGetSymbolAddress((void**)&bu,   g_bu);
    cudaGetSymbolAddress((void**)&y,    g_y);
    cudaGetSymbolAddress((void**)&gate, g_gate);
    cudaGetSymbolAddress((void**)&xres, g_xres);
    cudaGetSymbolAddress((void**)&h2,   g_h2);
    cudaGetSymbolAddress((void**)&hid,  g_hid);

    // 1) h1 = LN(x) (eps 1e-6)
    ln_kernel<kC, 128, false><<<kNTOK, 128>>>(x, nullptr, 0, 0, ln1_g, ln1_b, h1, 1e-6f);

    // 2) xz = h1 @ w_in   (16384 x 1536, K=384)
    sgemm_kernel<0><<<dim3(2 * kDI / 128, kNTOK / 128), 256>>>(
        h1, w_in, xz, kNTOK, 2 * kDI, kC, nullptr, nullptr);

    // 3) u = silu(dwconv3x3(xm))
    conv_silu_kernel<<<(kNTOK * kDI) / 256, 256>>>(xz, conv_w, u);

    // 4) dtbc = u @ x_proj_w  (26 outputs per token)
    xproj_kernel<<<kNTOK / 8, 256>>>(u, x_proj_w, dtbc);

    // 5) dt_proj + softplus; a = exp(dt*A), bu = dt*B*u
    dt_kernel<<<(kNTOK * kDI) / 256, 256>>>(dtbc, dt_proj_w, dt_proj_b, A_log, u, a, bu);

    // 6) selective scan -> y
    scan_kernel<<<kB * 3, 256>>>(a, bu, u, dtbc, Dp, y);

    // 7) gate = LN_out(y) * silu(z)  (eps 1e-5, z = xz[:, DI:2DI])
    ln_kernel<kDI, 256, true><<<kNTOK, 256>>>(y, xz, 2 * kDI, kDI,
                                              outnorm_g, outnorm_b, gate, 1e-5f);

    // 8) xres = gate @ w_out + x
    sgemm_kernel<1><<<dim3(kC / 128, kNTOK / 128), 256>>>(
        gate, w_out, xres, kNTOK, kC, kDI, nullptr, x);

    // 9) h2 = LN(xres) (eps 1e-6)
    ln_kernel<kC, 128, false><<<kNTOK, 128>>>(xres, nullptr, 0, 0, ln2_g, ln2_b, h2, 1e-6f);

    // 10) hid = gelu(h2 @ fc1_w + fc1_b)
    sgemm_kernel<2><<<dim3(kHID / 128, kNTOK / 128), 256>>>(
        h2, fc1_w, hid, kNTOK, kHID, kC, fc1_b, nullptr);

    // 11) out = hid @ fc2_w + fc2_b + xres
    sgemm_kernel<3><<<dim3(kC / 128, kNTOK / 128), 256>>>(
        hid, fc2_w, out, kNTOK, kC, kHID, fc2_b, xres);
}

// round 5
// speedup vs baseline: 1.9037x; 1.9037x over previous
#include <cuda_runtime.h>
#include <math.h>
#include <stdint.h>

// ---------------------------------------------------------------------------
// Problem constants
// ---------------------------------------------------------------------------
constexpr int kB     = 16;
constexpr int kH     = 32;
constexpr int kW     = 32;
constexpr int kC     = 384;
constexpr int kDI    = 768;
constexpr int kDTR   = 24;
constexpr int kHID   = 1536;
constexpr int kL     = kH * kW;          // 1024
constexpr int kNTOK  = kB * kL;          // 16384
constexpr int kXPK   = kDTR + 2;         // 26

// ---------------------------------------------------------------------------
// Scratch
// ---------------------------------------------------------------------------
__device__ float g_h1  [(size_t)kNTOK * kC];
__device__ float g_xz  [(size_t)kNTOK * 2 * kDI];
__device__ float g_u   [(size_t)kNTOK * kDI];
__device__ float g_dtbc[(size_t)kNTOK * kXPK];
__device__ float g_a   [(size_t)kNTOK * kDI];
__device__ float g_bu  [(size_t)kNTOK * kDI];
__device__ float g_y   [(size_t)kNTOK * kDI];
__device__ float g_gate[(size_t)kNTOK * kDI];
__device__ float g_xres[(size_t)kNTOK * kC];
__device__ float g_h2  [(size_t)kNTOK * kC];
__device__ float g_hid [(size_t)kNTOK * kHID];
// transposed weights ([N,K] so GEMM B-operand is K-major)
__device__ float g_wt_in [(size_t)(2 * kDI) * kC];   // 1536 x 384
__device__ float g_wt_out[(size_t)kC * kDI];         // 384 x 768
__device__ float g_wt_f1 [(size_t)kHID * kC];        // 1536 x 384
__device__ float g_wt_f2 [(size_t)kC * kHID];        // 384 x 1536

// ---------------------------------------------------------------------------
// Math helpers
// ---------------------------------------------------------------------------
__device__ __forceinline__ float siluf(float x) { return x / (1.f + expf(-x)); }
__device__ __forceinline__ float softplusf(float x) {
    return fmaxf(x, 0.f) + log1pf(expf(-fabsf(x)));
}
__device__ __forceinline__ float gelu_tanh(float x) {
    float x3 = x * x * x;
    return 0.5f * x * (1.f + tanhf(0.7978845608028654f * (x + 0.044715f * x3)));
}

// ---------------------------------------------------------------------------
// PTX helpers (sm_80-safe only: cp.async + mma.sync)
// ---------------------------------------------------------------------------
__device__ __forceinline__ uint32_t smem_to_u32(const void* p) {
    uint32_t a;
    asm("{ .reg .u64 t; cvta.to.shared.u64 t, %1; cvt.u32.u64 %0, t; }" : "=r"(a) : "l"(p));
    return a;
}
__device__ __forceinline__ void cp_async16(uint32_t sa, const void* g) {
    asm volatile("cp.async.cg.shared.global [%0], [%1], 16;" :: "r"(sa), "l"(g));
}
__device__ __forceinline__ void cp_commit() { asm volatile("cp.async.commit_group;" ::: "memory"); }
template <int N>
__device__ __forceinline__ void cp_wait() { asm volatile("cp.async.wait_group %0;" :: "n"(N) : "memory"); }

__device__ __forceinline__ uint32_t to_tf32(float v) {
    uint32_t u;
    asm("cvt.rna.tf32.f32 %0, %1;" : "=r"(u) : "f"(v));
    return u;
}
__device__ __forceinline__ void mma_tf32(float* c, const uint32_t* a, const uint32_t* b) {
    asm volatile(
        "mma.sync.aligned.m16n8k8.row.col.f32.tf32.tf32.f32 "
        "{%0,%1,%2,%3}, {%4,%5,%6,%7}, {%8,%9}, {%0,%1,%2,%3};"
        : "+f"(c[0]), "+f"(c[1]), "+f"(c[2]), "+f"(c[3])
        : "r"(a[0]), "r"(a[1]), "r"(a[2]), "r"(a[3]), "r"(b[0]), "r"(b[1]));
}

// ---------------------------------------------------------------------------
// tf32 mma.sync GEMM: C[M,N] = A[M,K] @ Bt[N,K]^T  (+ fused epilogue)
//   EPI: 0=store  1=+resid  2=+bias->gelu  3=+bias+resid
//   BM=BN=128, BK=16, DEPTH=4 cp.async stages, 256 threads (8 warps, 2x4).
//   Each warp: 64x32 output = 4x4 tiles of m16n8k8.
// ---------------------------------------------------------------------------
template <int EPI>
__global__ __launch_bounds__(256) void mma_gemm(
    const float* __restrict__ A, const float* __restrict__ Bt,
    float* __restrict__ C, int M, int N, int K,
    const float* __restrict__ bias, const float* __restrict__ resid)
{
    constexpr int BM = 128, BN = 128, BK = 16, BKP = 20, DEPTH = 4;
    constexpr int A_ELEMS = BM * BKP;   // 2560 floats / stage
    constexpr int B_ELEMS = BN * BKP;

    extern __shared__ float sm[];
    float* sA = sm;                          // [DEPTH][BM][BKP]
    float* sB = sm + DEPTH * A_ELEMS;        // [DEPTH][BN][BKP]
    const uint32_t sAu = smem_to_u32(sA);
    const uint32_t sBu = smem_to_u32(sB);

    const int tid  = threadIdx.x;
    const int wid  = tid >> 5, lane = tid & 31;
    const int grp  = lane >> 2, tg = lane & 3;
    const int m_w  = (wid & 1) * 64;          // warp row offset in tile
    const int n_w  = (wid >> 1) * 32;         // warp col offset in tile
    const int tile_m = blockIdx.y * BM;
    const int tile_n = blockIdx.x * BN;

    const int nst = K / BK;

    // each thread loads 2 x 16B chunks for A and 2 for B per stage
    const int ld_row = tid >> 2;   // 0..63
    const int ld_seg = tid & 3;    // 0..3 (16B segment within 64B row chunk)

    auto load_stage = [&](int s) {
        const int slot = s % DEPTH;
        const int k0 = s * BK;
        const float* ap = A + (size_t)tile_m * K + k0;
        const uint32_t da = sAu + (uint32_t)(slot * A_ELEMS) * 4u;
#pragma unroll
        for (int p = 0; p < 2; p++) {
            const int row = ld_row + p * 64;
            cp_async16(da + (uint32_t)(row * BKP + ld_seg * 4) * 4u,
                       ap + (size_t)row * K + ld_seg * 4);
        }
        const float* bp = Bt + (size_t)tile_n * K + k0;
        const uint32_t db = sBu + (uint32_t)(slot * B_ELEMS) * 4u;
#pragma unroll
        for (int p = 0; p < 2; p++) {
            const int row = ld_row + p * 64;
            cp_async16(db + (uint32_t)(row * BKP + ld_seg * 4) * 4u,
                       bp + (size_t)row * K + ld_seg * 4);
        }
        cp_commit();
    };

    float acc[4][4][4];
#pragma unroll
    for (int i = 0; i < 4; i++)
#pragma unroll
        for (int j = 0; j < 4; j++)
#pragma unroll
            for (int r = 0; r < 4; r++) acc[i][j][r] = 0.f;

    // prologue: stages 0 .. DEPTH-2
    const int pre = (nst < DEPTH - 1) ? nst : (DEPTH - 1);
    for (int s = 0; s < pre; s++) load_stage(s);

    for (int s = 0; s < nst; s++) {
        cp_wait<DEPTH - 2>();
        __syncthreads();

        const int nxt = s + DEPTH - 1;
        if (nxt < nst) load_stage(nxt);

        const int slot = s % DEPTH;
        const float* Ab = sA + slot * A_ELEMS + (m_w + grp) * BKP + tg;
        const float* Bb = sB + slot * B_ELEMS + (n_w + grp) * BKP + tg;

#pragma unroll
        for (int kk = 0; kk < 2; kk++) {
            const int k0 = kk * 8;
            uint32_t af[4][4];
#pragma unroll
            for (int i = 0; i < 4; i++) {
                const float* ar = Ab + i * 16 * BKP + k0;
                af[i][0] = to_tf32(ar[0]);
                af[i][1] = to_tf32(ar[8 * BKP]);
                af[i][2] = to_tf32(ar[4]);
                af[i][3] = to_tf32(ar[8 * BKP + 4]);
            }
            uint32_t bf[4][2];
#pragma unroll
            for (int j = 0; j < 4; j++) {
                const float* br = Bb + j * 8 * BKP + k0;
                bf[j][0] = to_tf32(br[0]);
                bf[j][1] = to_tf32(br[4]);
            }
#pragma unroll
            for (int i = 0; i < 4; i++)
#pragma unroll
                for (int j = 0; j < 4; j++)
                    mma_tf32(acc[i][j], af[i], bf[j]);
        }
        __syncthreads();
    }

    // ---- Epilogue ----
#pragma unroll
    for (int i = 0; i < 4; i++) {
        const int rg0 = tile_m + m_w + i * 16 + grp;
#pragma unroll
        for (int j = 0; j < 4; j++) {
            const int cg = tile_n + n_w + j * 8 + tg * 2;
#pragma unroll
            for (int h = 0; h < 2; h++) {       // h=0: rows grp, h=1: rows grp+8
                const int rg = rg0 + h * 8;
                float2 v = make_float2(acc[i][j][h * 2], acc[i][j][h * 2 + 1]);
                const size_t off = (size_t)rg * N + cg;
                if (EPI == 1) {
                    float2 rr = *reinterpret_cast<const float2*>(resid + off);
                    v.x += rr.x; v.y += rr.y;
                }
                if (EPI == 2) {
                    float2 bb = *reinterpret_cast<const float2*>(bias + cg);
                    v.x = gelu_tanh(v.x + bb.x);
                    v.y = gelu_tanh(v.y + bb.y);
                }
                if (EPI == 3) {
                    float2 bb = *reinterpret_cast<const float2*>(bias + cg);
                    float2 rr = *reinterpret_cast<const float2*>(resid + off);
                    v.x += bb.x + rr.x; v.y += bb.y + rr.y;
                }
                *reinterpret_cast<float2*>(C + off) = v;
            }
        }
    }
}

// ---------------------------------------------------------------------------
// 32x32 tiled transpose: out[N,K] = in[K,N]^T
// ---------------------------------------------------------------------------
__global__ void transpose_kernel(const float* __restrict__ in,
                                 float* __restrict__ out, int K, int N)
{
    __shared__ float t[32][33];
    const int n0 = blockIdx.x * 32, k0 = blockIdx.y * 32;
    const int x = threadIdx.x, y = threadIdx.y;
#pragma unroll
    for (int i = y; i < 32; i += 8)
        t[i][x] = in[(size_t)(k0 + i) * N + n0 + x];
    __syncthreads();
#pragma unroll
    for (int i = y; i < 32; i += 8)
        out[(size_t)(n0 + i) * K + k0 + x] = t[x][i];
}

// ---------------------------------------------------------------------------
// LayerNorm (optionally fused with * silu(z))
// ---------------------------------------------------------------------------
template <int CH, int TPB, bool MUL_SILU>
__global__ __launch_bounds__(TPB) void ln_kernel(
    const float* __restrict__ in,
    const float* __restrict__ zsrc, int zld, int zoff,
    const float* __restrict__ gam, const float* __restrict__ bet,
    float* __restrict__ out, float eps)
{
    constexpr int PER = CH / TPB;
    const int n = blockIdx.x;
    const float* row = in + (size_t)n * CH;

    float v[PER];
    float s = 0.f, s2 = 0.f;
#pragma unroll
    for (int i = 0; i < PER; i++) {
        float t = row[i * TPB + threadIdx.x];
        v[i] = t; s += t; s2 += t * t;
    }
    __shared__ float sm[2 * (TPB / 32)];
#pragma unroll
    for (int o = 16; o; o >>= 1) {
        s  += __shfl_down_sync(0xffffffffu, s,  o);
        s2 += __shfl_down_sync(0xffffffffu, s2, o);
    }
    const int wid = threadIdx.x >> 5, lid = threadIdx.x & 31;
    if (lid == 0) { sm[wid] = s; sm[TPB / 32 + wid] = s2; }
    __syncthreads();
    if (threadIdx.x == 0) {
        float a = 0.f, b = 0.f;
#pragma unroll
        for (int i = 0; i < TPB / 32; i++) { a += sm[i]; b += sm[TPB / 32 + i]; }
        sm[0] = a; sm[1] = b;
    }
    __syncthreads();
    const float mu  = sm[0] * (1.f / CH);
    const float var = sm[1] * (1.f / CH) - mu * mu;
    const float inv = rsqrtf(var + eps);
#pragma unroll
    for (int i = 0; i < PER; i++) {
        const int c = i * TPB + threadIdx.x;
        float o = (v[i] - mu) * inv * gam[c] + bet[c];
        if (MUL_SILU) {
            float z = zsrc[(size_t)n * zld + zoff + c];
            o *= siluf(z);
        }
        out[(size_t)n * CH + c] = o;
    }
}

// ---------------------------------------------------------------------------
// Depthwise 3x3 SAME conv + silu
// ---------------------------------------------------------------------------
__global__ void conv_silu_kernel(const float* __restrict__ xz,
                                 const float* __restrict__ cw,
                                 float* __restrict__ u)
{
    const int idx = blockIdx.x * blockDim.x + threadIdx.x;
    if (idx >= kNTOK * kDI) return;
    const int d = idx % kDI;
    const int n = idx / kDI;
    const int w = n % kW;
    const int h = (n / kW) % kH;

    float acc = 0.f;
#pragma unroll
    for (int ky = 0; ky < 3; ky++) {
        const int hh = h + ky - 1;
        if (hh < 0 || hh >= kH) continue;
#pragma unroll
        for (int kx = 0; kx < 3; kx++) {
            const int ww = w + kx - 1;
            if (ww < 0 || ww >= kW) continue;
            const int nn = n + (ky - 1) * kW + (kx - 1);
            acc = fmaf(cw[d * 9 + ky * 3 + kx], xz[(size_t)nn * (2 * kDI) + d], acc);
        }
    }
    u[idx] = siluf(acc);
}

// ---------------------------------------------------------------------------
// x_proj (768 -> 26) — warp per token
// ---------------------------------------------------------------------------
__global__ __launch_bounds__(256) void xproj_kernel(
    const float* __restrict__ u, const float* __restrict__ W,
    float* __restrict__ out)
{
    __shared__ float sW[64 * kXPK];
    const int warp = threadIdx.x >> 5, lane = threadIdx.x & 31;
    const int n = blockIdx.x * 8 + warp;
    float acc = 0.f;

    for (int j0 = 0; j0 < kDI; j0 += 64) {
        for (int i = threadIdx.x; i < 64 * kXPK; i += 256)
            sW[i] = W[j0 * kXPK + i];
        __syncthreads();

        const float uv0 = u[(size_t)n * kDI + j0 + lane];
        const float uv1 = u[(size_t)n * kDI + j0 + 32 + lane];
#pragma unroll
        for (int jj = 0; jj < 32; jj++) {
            const float uj = __shfl_sync(0xffffffffu, uv0, jj);
            if (lane < kXPK) acc = fmaf(uj, sW[jj * kXPK + lane], acc);
        }
#pragma unroll
        for (int jj = 0; jj < 32; jj++) {
            const float uj = __shfl_sync(0xffffffffu, uv1, jj);
            if (lane < kXPK) acc = fmaf(uj, sW[(32 + jj) * kXPK + lane], acc);
        }
        __syncthreads();
    }
    if (lane < kXPK) out[(size_t)n * kXPK + lane] = acc;
}

// ---------------------------------------------------------------------------
// dt_proj + softplus + scan coefficients
// ---------------------------------------------------------------------------
__global__ void dt_kernel(const float* __restrict__ dtbc,
                          const float* __restrict__ dtw,
                          const float* __restrict__ dtb,
                          const float* __restrict__ A_log,
                          const float* __restrict__ u,
                          float* __restrict__ a, float* __restrict__ bu)
{
    const int idx = blockIdx.x * blockDim.x + threadIdx.x;
    if (idx >= kNTOK * kDI) return;
    const int d = idx % kDI;
    const int n = idx / kDI;
    const float* r = dtbc + (size_t)n * kXPK;

    float acc = dtb[d];
#pragma unroll
    for (int j = 0; j < kDTR; j++)
        acc = fmaf(r[j], dtw[j * kDI + d], acc);

    const float dtv = softplusf(acc);
    const float Ad  = -expf(A_log[d]);
    a[idx]  = expf(dtv * Ad);
    bu[idx] = dtv * r[kDTR] * u[idx];
}

// ---------------------------------------------------------------------------
// Selective scan (DS=1)
// ---------------------------------------------------------------------------
__global__ __launch_bounds__(256) void scan_kernel(
    const float* __restrict__ a, const float* __restrict__ bu,
    const float* __restrict__ u, const float* __restrict__ dtbc,
    const float* __restrict__ Dp, float* __restrict__ y)
{
    const int b = blockIdx.x / 3;
    const int d = (blockIdx.x % 3) * 256 + threadIdx.x;
    const float Dd = Dp[d];
    float h = 0.f;
    const size_t base = (size_t)b * kL * kDI + d;
    const size_t cbase = (size_t)b * kL;
#pragma unroll 4
    for (int l = 0; l < kL; l++) {
        const size_t idx = base + (size_t)l * kDI;
        const float cc = __ldg(&dtbc[(cbase + l) * kXPK + (kDTR + 1)]);
        h = fmaf(a[idx], h, bu[idx]);
        y[idx] = fmaf(h, cc, u[idx] * Dd);
    }
}

// ---------------------------------------------------------------------------
// Launch
// ---------------------------------------------------------------------------
extern "C" void kernel_launch(void* const* d_in, const int* in_sizes, int n_in,
                              void* d_out, int out_size)
{
    const float* x         = (const float*)d_in[0];
    const float* ln1_g     = (const float*)d_in[1];
    const float* ln1_b     = (const float*)d_in[2];
    const float* w_in      = (const float*)d_in[3];
    const float* conv_w    = (const float*)d_in[4];
    const float* x_proj_w  = (const float*)d_in[5];
    const float* dt_proj_w = (const float*)d_in[6];
    const float* dt_proj_b = (const float*)d_in[7];
    const float* A_log     = (const float*)d_in[8];
    const float* Dp        = (const float*)d_in[9];
    const float* outnorm_g = (const float*)d_in[10];
    const float* outnorm_b = (const float*)d_in[11];
    const float* w_out     = (const float*)d_in[12];
    const float* ln2_g     = (const float*)d_in[13];
    const float* ln2_b     = (const float*)d_in[14];
    const float* fc1_w     = (const float*)d_in[15];
    const float* fc1_b     = (const float*)d_in[16];
    const float* fc2_w     = (const float*)d_in[17];
    const float* fc2_b     = (const float*)d_in[18];
    float* out = (float*)d_out;

    float *h1, *xz, *u, *dtbc, *a, *bu, *y, *gate, *xres, *h2, *hid;
    float *wt_in, *wt_out, *wt_f1, *wt_f2;
    cudaGetSymbolAddress((void**)&h1,    g_h1);
    cudaGetSymbolAddress((void**)&xz,    g_xz);
    cudaGetSymbolAddress((void**)&u,     g_u);
    cudaGetSymbolAddress((void**)&dtbc,  g_dtbc);
    cudaGetSymbolAddress((void**)&a,     g_a);
    cudaGetSymbolAddress((void**)&bu,    g_bu);
    cudaGetSymbolAddress((void**)&y,     g_y);
    cudaGetSymbolAddress((void**)&gate,  g_gate);
    cudaGetSymbolAddress((void**)&xres,  g_xres);
    cudaGetSymbolAddress((void**)&h2,    g_h2);
    cudaGetSymbolAddress((void**)&hid,   g_hid);
    cudaGetSymbolAddress((void**)&wt_in, g_wt_in);
    cudaGetSymbolAddress((void**)&wt_out,g_wt_out);
    cudaGetSymbolAddress((void**)&wt_f1, g_wt_f1);
    cudaGetSymbolAddress((void**)&wt_f2, g_wt_f2);

    // dynamic smem: DEPTH * (BM + BN) * BKP floats = 4 * 256 * 20 * 4B = 80 KB
    const int SMEM = 4 * 256 * 20 * 4;
    cudaFuncSetAttribute(mma_gemm<0>, cudaFuncAttributeMaxDynamicSharedMemorySize, SMEM);
    cudaFuncSetAttribute(mma_gemm<1>, cudaFuncAttributeMaxDynamicSharedMemorySize, SMEM);
    cudaFuncSetAttribute(mma_gemm<2>, cudaFuncAttributeMaxDynamicSharedMemorySize, SMEM);
    cudaFuncSetAttribute(mma_gemm<3>, cudaFuncAttributeMaxDynamicSharedMemorySize, SMEM);

    // 0) transpose weights to [N,K]
    transpose_kernel<<<dim3(2 * kDI / 32, kC / 32),  dim3(32, 8)>>>(w_in,  wt_in,  kC,   2 * kDI);
    transpose_kernel<<<dim3(kC / 32,      kDI / 32), dim3(32, 8)>>>(w_out, wt_out, kDI,  kC);
    transpose_kernel<<<dim3(kHID / 32,    kC / 32),  dim3(32, 8)>>>(fc1_w, wt_f1,  kC,   kHID);
    transpose_kernel<<<dim3(kC / 32,      kHID / 32),dim3(32, 8)>>>(fc2_w, wt_f2,  kHID, kC);

    // 1) h1 = LN(x)
    ln_kernel<kC, 128, false><<<kNTOK, 128>>>(x, nullptr, 0, 0, ln1_g, ln1_b, h1, 1e-6f);

    // 2) xz = h1 @ w_in   (M=16384, N=1536, K=384)
    mma_gemm<0><<<dim3((2 * kDI) / 128, kNTOK / 128), 256, SMEM>>>(
        h1, wt_in, xz, kNTOK, 2 * kDI, kC, nullptr, nullptr);

    // 3) u = silu(dwconv3x3(xm))
    conv_silu_kernel<<<(kNTOK * kDI) / 256, 256>>>(xz, conv_w, u);

    // 4) dtbc = u @ x_proj_w
    xproj_kernel<<<kNTOK / 8, 256>>>(u, x_proj_w, dtbc);

    // 5) dt coefficients
    dt_kernel<<<(kNTOK * kDI) / 256, 256>>>(dtbc, dt_proj_w, dt_proj_b, A_log, u, a, bu);

    // 6) selective scan
    scan_kernel<<<kB * 3, 256>>>(a, bu, u, dtbc, Dp, y);

    // 7) gate = LN_out(y) * silu(z)
    ln_kernel<kDI, 256, true><<<kNTOK, 256>>>(y, xz, 2 * kDI, kDI,
                                              outnorm_g, outnorm_b, gate, 1e-5f);

    // 8) xres = gate @ w_out + x   (N=384, K=768)
    mma_gemm<1><<<dim3(kC / 128, kNTOK / 128), 256, SMEM>>>(
        gate, wt_out, xres, kNTOK, kC, kDI, nullptr, x);

    // 9) h2 = LN(xres)
    ln_kernel<kC, 128, false><<<kNTOK, 128>>>(xres, nullptr, 0, 0, ln2_g, ln2_b, h2, 1e-6f);

    // 10) hid = gelu(h2 @ fc1_w + fc1_b)   (N=1536, K=384)
    mma_gemm<2><<<dim3(kHID / 128, kNTOK / 128), 256, SMEM>>>(
        h2, wt_f1, hid, kNTOK, kHID, kC, fc1_b, nullptr);

    // 11) out = hid @ fc2_w + fc2_b + xres   (N=384, K=1536)
    mma_gemm<3><<<dim3(kC / 128, kNTOK / 128), 256, SMEM>>>(
        hid, wt_f2, out, kNTOK, kC, kHID, fc2_b, xres);
}

// round 6
// speedup vs baseline: 1.9211x; 1.0091x over previous
#include <cuda_runtime.h>
#include <math.h>
#include <stdint.h>

// ---------------------------------------------------------------------------
// Problem constants
// ---------------------------------------------------------------------------
constexpr int kB     = 16;
constexpr int kH     = 32;
constexpr int kW     = 32;
constexpr int kC     = 384;
constexpr int kDI    = 768;
constexpr int kDTR   = 24;
constexpr int kHID   = 1536;
constexpr int kL     = kH * kW;          // 1024
constexpr int kNTOK  = kB * kL;          // 16384
constexpr int kXPK   = kDTR + 2;         // 26

// ---------------------------------------------------------------------------
// Scratch
// ---------------------------------------------------------------------------
__device__ float g_h1  [(size_t)kNTOK * kC];
__device__ float g_xz  [(size_t)kNTOK * 2 * kDI];
__device__ float g_u   [(size_t)kNTOK * kDI];
__device__ float g_dtbc[(size_t)kNTOK * kXPK];
__device__ float g_a   [(size_t)kNTOK * kDI];
__device__ float g_bu  [(size_t)kNTOK * kDI];
__device__ float g_y   [(size_t)kNTOK * kDI];
__device__ float g_gate[(size_t)kNTOK * kDI];
__device__ float g_xres[(size_t)kNTOK * kC];
__device__ float g_h2  [(size_t)kNTOK * kC];
__device__ float g_hid [(size_t)kNTOK * kHID];
// transposed weights ([N,K] so GEMM B-operand is K-major)
__device__ float g_wt_in [(size_t)(2 * kDI) * kC];   // 1536 x 384
__device__ float g_wt_out[(size_t)kC * kDI];         // 384 x 768
__device__ float g_wt_f1 [(size_t)kHID * kC];        // 1536 x 384
__device__ float g_wt_f2 [(size_t)kC * kHID];        // 384 x 1536

// ---------------------------------------------------------------------------
// Math helpers
// ---------------------------------------------------------------------------
__device__ __forceinline__ float siluf(float x) { return x / (1.f + expf(-x)); }
__device__ __forceinline__ float softplusf(float x) {
    return fmaxf(x, 0.f) + log1pf(expf(-fabsf(x)));
}
__device__ __forceinline__ float gelu_tanh(float x) {
    float x3 = x * x * x;
    return 0.5f * x * (1.f + tanhf(0.7978845608028654f * (x + 0.044715f * x3)));
}

// ---------------------------------------------------------------------------
// PTX helpers (sm_80-safe only: cp.async + mma.sync)
// ---------------------------------------------------------------------------
__device__ __forceinline__ uint32_t smem_to_u32(const void* p) {
    uint32_t a;
    asm("{ .reg .u64 t; cvta.to.shared.u64 t, %1; cvt.u32.u64 %0, t; }" : "=r"(a) : "l"(p));
    return a;
}
__device__ __forceinline__ void cp_async16(uint32_t sa, const void* g) {
    asm volatile("cp.async.cg.shared.global [%0], [%1], 16;" :: "r"(sa), "l"(g));
}
__device__ __forceinline__ void cp_commit() { asm volatile("cp.async.commit_group;" ::: "memory"); }
template <int N>
__device__ __forceinline__ void cp_wait() { asm volatile("cp.async.wait_group %0;" :: "n"(N) : "memory"); }

__device__ __forceinline__ uint32_t to_tf32(float v) {
    uint32_t u;
    asm("cvt.rna.tf32.f32 %0, %1;" : "=r"(u) : "f"(v));
    return u;
}
__device__ __forceinline__ void mma_tf32(float* c, const uint32_t* a, const uint32_t* b) {
    asm volatile(
        "mma.sync.aligned.m16n8k8.row.col.f32.tf32.tf32.f32 "
        "{%0,%1,%2,%3}, {%4,%5,%6,%7}, {%8,%9}, {%0,%1,%2,%3};"
        : "+f"(c[0]), "+f"(c[1]), "+f"(c[2]), "+f"(c[3])
        : "r"(a[0]), "r"(a[1]), "r"(a[2]), "r"(a[3]), "r"(b[0]), "r"(b[1]));
}

// ---------------------------------------------------------------------------
// tf32 mma.sync GEMM: C[M,N] = A[M,K] @ Bt[N,K]^T  (+ fused epilogue)
//   EPI: 0=store  1=+resid  2=+bias->gelu  3=+bias+resid
//   BM=BN=128, BK=16, DEPTH=4 cp.async stages, 256 threads (8 warps, 2x4).
//   Each warp: 64x32 output = 4x4 tiles of m16n8k8.
// ---------------------------------------------------------------------------
template <int EPI>
__global__ __launch_bounds__(256) void mma_gemm(
    const float* __restrict__ A, const float* __restrict__ Bt,
    float* __restrict__ C, int M, int N, int K,
    const float* __restrict__ bias, const float* __restrict__ resid)
{
    constexpr int BM = 128, BN = 128, BK = 16, BKP = 20, DEPTH = 4;
    constexpr int A_ELEMS = BM * BKP;   // 2560 floats / stage
    constexpr int B_ELEMS = BN * BKP;

    extern __shared__ float sm[];
    float* sA = sm;                          // [DEPTH][BM][BKP]
    float* sB = sm + DEPTH * A_ELEMS;        // [DEPTH][BN][BKP]
    const uint32_t sAu = smem_to_u32(sA);
    const uint32_t sBu = smem_to_u32(sB);

    const int tid  = threadIdx.x;
    const int wid  = tid >> 5, lane = tid & 31;
    const int grp  = lane >> 2, tg = lane & 3;
    const int m_w  = (wid & 1) * 64;          // warp row offset in tile
    const int n_w  = (wid >> 1) * 32;         // warp col offset in tile
    const int tile_m = blockIdx.y * BM;
    const int tile_n = blockIdx.x * BN;

    const int nst = K / BK;

    // each thread loads 2 x 16B chunks for A and 2 for B per stage
    const int ld_row = tid >> 2;   // 0..63
    const int ld_seg = tid & 3;    // 0..3 (16B segment within 64B row chunk)

    auto load_stage = [&](int s) {
        const int slot = s % DEPTH;
        const int k0 = s * BK;
        const float* ap = A + (size_t)tile_m * K + k0;
        const uint32_t da = sAu + (uint32_t)(slot * A_ELEMS) * 4u;
#pragma unroll
        for (int p = 0; p < 2; p++) {
            const int row = ld_row + p * 64;
            cp_async16(da + (uint32_t)(row * BKP + ld_seg * 4) * 4u,
                       ap + (size_t)row * K + ld_seg * 4);
        }
        const float* bp = Bt + (size_t)tile_n * K + k0;
        const uint32_t db = sBu + (uint32_t)(slot * B_ELEMS) * 4u;
#pragma unroll
        for (int p = 0; p < 2; p++) {
            const int row = ld_row + p * 64;
            cp_async16(db + (uint32_t)(row * BKP + ld_seg * 4) * 4u,
                       bp + (size_t)row * K + ld_seg * 4);
        }
        cp_commit();
    };

    float acc[4][4][4];
#pragma unroll
    for (int i = 0; i < 4; i++)
#pragma unroll
        for (int j = 0; j < 4; j++)
#pragma unroll
            for (int r = 0; r < 4; r++) acc[i][j][r] = 0.f;

    // prologue: stages 0 .. DEPTH-2
    const int pre = (nst < DEPTH - 1) ? nst : (DEPTH - 1);
    for (int s = 0; s < pre; s++) load_stage(s);

    for (int s = 0; s < nst; s++) {
        cp_wait<DEPTH - 2>();
        __syncthreads();

        const int nxt = s + DEPTH - 1;
        if (nxt < nst) load_stage(nxt);

        const int slot = s % DEPTH;
        const float* Ab = sA + slot * A_ELEMS + (m_w + grp) * BKP + tg;
        const float* Bb = sB + slot * B_ELEMS + (n_w + grp) * BKP + tg;

#pragma unroll
        for (int kk = 0; kk < 2; kk++) {
            const int k0 = kk * 8;
            uint32_t af[4][4];
#pragma unroll
            for (int i = 0; i < 4; i++) {
                const float* ar = Ab + i * 16 * BKP + k0;
                af[i][0] = to_tf32(ar[0]);
                af[i][1] = to_tf32(ar[8 * BKP]);
                af[i][2] = to_tf32(ar[4]);
                af[i][3] = to_tf32(ar[8 * BKP + 4]);
            }
            uint32_t bf[4][2];
#pragma unroll
            for (int j = 0; j < 4; j++) {
                const float* br = Bb + j * 8 * BKP + k0;
                bf[j][0] = to_tf32(br[0]);
                bf[j][1] = to_tf32(br[4]);
            }
#pragma unroll
            for (int i = 0; i < 4; i++)
#pragma unroll
                for (int j = 0; j < 4; j++)
                    mma_tf32(acc[i][j], af[i], bf[j]);
        }
        __syncthreads();
    }

    // ---- Epilogue ----
#pragma unroll
    for (int i = 0; i < 4; i++) {
        const int rg0 = tile_m + m_w + i * 16 + grp;
#pragma unroll
        for (int j = 0; j < 4; j++) {
            const int cg = tile_n + n_w + j * 8 + tg * 2;
#pragma unroll
            for (int h = 0; h < 2; h++) {       // h=0: rows grp, h=1: rows grp+8
                const int rg = rg0 + h * 8;
                float2 v = make_float2(acc[i][j][h * 2], acc[i][j][h * 2 + 1]);
                const size_t off = (size_t)rg * N + cg;
                if (EPI == 1) {
                    float2 rr = *reinterpret_cast<const float2*>(resid + off);
                    v.x += rr.x; v.y += rr.y;
                }
                if (EPI == 2) {
                    float2 bb = *reinterpret_cast<const float2*>(bias + cg);
                    v.x = gelu_tanh(v.x + bb.x);
                    v.y = gelu_tanh(v.y + bb.y);
                }
                if (EPI == 3) {
                    float2 bb = *reinterpret_cast<const float2*>(bias + cg);
                    float2 rr = *reinterpret_cast<const float2*>(resid + off);
                    v.x += bb.x + rr.x; v.y += bb.y + rr.y;
                }
                *reinterpret_cast<float2*>(C + off) = v;
            }
        }
    }
}

// ---------------------------------------------------------------------------
// 32x32 tiled transpose: out[N,K] = in[K,N]^T
// ---------------------------------------------------------------------------
__global__ void transpose_kernel(const float* __restrict__ in,
                                 float* __restrict__ out, int K, int N)
{
    __shared__ float t[32][33];
    const int n0 = blockIdx.x * 32, k0 = blockIdx.y * 32;
    const int x = threadIdx.x, y = threadIdx.y;
#pragma unroll
    for (int i = y; i < 32; i += 8)
        t[i][x] = in[(size_t)(k0 + i) * N + n0 + x];
    __syncthreads();
#pragma unroll
    for (int i = y; i < 32; i += 8)
        out[(size_t)(n0 + i) * K + k0 + x] = t[x][i];
}

// ---------------------------------------------------------------------------
// LayerNorm (optionally fused with * silu(z))
// ---------------------------------------------------------------------------
template <int CH, int TPB, bool MUL_SILU>
__global__ __launch_bounds__(TPB) void ln_kernel(
    const float* __restrict__ in,
    const float* __restrict__ zsrc, int zld, int zoff,
    const float* __restrict__ gam, const float* __restrict__ bet,
    float* __restrict__ out, float eps)
{
    constexpr int PER = CH / TPB;
    const int n = blockIdx.x;
    const float* row = in + (size_t)n * CH;

    float v[PER];
    float s = 0.f, s2 = 0.f;
#pragma unroll
    for (int i = 0; i < PER; i++) {
        float t = row[i * TPB + threadIdx.x];
        v[i] = t; s += t; s2 += t * t;
    }
    __shared__ float sm[2 * (TPB / 32)];
#pragma unroll
    for (int o = 16; o; o >>= 1) {
        s  += __shfl_down_sync(0xffffffffu, s,  o);
        s2 += __shfl_down_sync(0xffffffffu, s2, o);
    }
    const int wid = threadIdx.x >> 5, lid = threadIdx.x & 31;
    if (lid == 0) { sm[wid] = s; sm[TPB / 32 + wid] = s2; }
    __syncthreads();
    if (threadIdx.x == 0) {
        float a = 0.f, b = 0.f;
#pragma unroll
        for (int i = 0; i < TPB / 32; i++) { a += sm[i]; b += sm[TPB / 32 + i]; }
        sm[0] = a; sm[1] = b;
    }
    __syncthreads();
    const float mu  = sm[0] * (1.f / CH);
    const float var = sm[1] * (1.f / CH) - mu * mu;
    const float inv = rsqrtf(var + eps);
#pragma unroll
    for (int i = 0; i < PER; i++) {
        const int c = i * TPB + threadIdx.x;
        float o = (v[i] - mu) * inv * gam[c] + bet[c];
        if (MUL_SILU) {
            float z = zsrc[(size_t)n * zld + zoff + c];
            o *= siluf(z);
        }
        out[(size_t)n * CH + c] = o;
    }
}

// ---------------------------------------------------------------------------
// Depthwise 3x3 SAME conv + silu
// ---------------------------------------------------------------------------
__global__ void conv_silu_kernel(const float* __restrict__ xz,
                                 const float* __restrict__ cw,
                                 float* __restrict__ u)
{
    const int idx = blockIdx.x * blockDim.x + threadIdx.x;
    if (idx >= kNTOK * kDI) return;
    const int d = idx % kDI;
    const int n = idx / kDI;
    const int w = n % kW;
    const int h = (n / kW) % kH;

    float acc = 0.f;
#pragma unroll
    for (int ky = 0; ky < 3; ky++) {
        const int hh = h + ky - 1;
        if (hh < 0 || hh >= kH) continue;
#pragma unroll
        for (int kx = 0; kx < 3; kx++) {
            const int ww = w + kx - 1;
            if (ww < 0 || ww >= kW) continue;
            const int nn = n + (ky - 1) * kW + (kx - 1);
            acc = fmaf(cw[d * 9 + ky * 3 + kx], xz[(size_t)nn * (2 * kDI) + d], acc);
        }
    }
    u[idx] = siluf(acc);
}

// ---------------------------------------------------------------------------
// x_proj (768 -> 26) — warp per token
// ---------------------------------------------------------------------------
__global__ __launch_bounds__(256) void xproj_kernel(
    const float* __restrict__ u, const float* __restrict__ W,
    float* __restrict__ out)
{
    __shared__ float sW[64 * kXPK];
    const int warp = threadIdx.x >> 5, lane = threadIdx.x & 31;
    const int n = blockIdx.x * 8 + warp;
    float acc = 0.f;

    for (int j0 = 0; j0 < kDI; j0 += 64) {
        for (int i = threadIdx.x; i < 64 * kXPK; i += 256)
            sW[i] = W[j0 * kXPK + i];
        __syncthreads();

        const float uv0 = u[(size_t)n * kDI + j0 + lane];
        const float uv1 = u[(size_t)n * kDI + j0 + 32 + lane];
#pragma unroll
        for (int jj = 0; jj < 32; jj++) {
            const float uj = __shfl_sync(0xffffffffu, uv0, jj);
            if (lane < kXPK) acc = fmaf(uj, sW[jj * kXPK + lane], acc);
        }
#pragma unroll
        for (int jj = 0; jj < 32; jj++) {
            const float uj = __shfl_sync(0xffffffffu, uv1, jj);
            if (lane < kXPK) acc = fmaf(uj, sW[(32 + jj) * kXPK + lane], acc);
        }
        __syncthreads();
    }
    if (lane < kXPK) out[(size_t)n * kXPK + lane] = acc;
}

// ---------------------------------------------------------------------------
// dt_proj + softplus + scan coefficients
// ---------------------------------------------------------------------------
__global__ void dt_kernel(const float* __restrict__ dtbc,
                          const float* __restrict__ dtw,
                          const float* __restrict__ dtb,
                          const float* __restrict__ A_log,
                          const float* __restrict__ u,
                          float* __restrict__ a, float* __restrict__ bu)
{
    const int idx = blockIdx.x * blockDim.x + threadIdx.x;
    if (idx >= kNTOK * kDI) return;
    const int d = idx % kDI;
    const int n = idx / kDI;
    const float* r = dtbc + (size_t)n * kXPK;

    float acc = dtb[d];
#pragma unroll
    for (int j = 0; j < kDTR; j++)
        acc = fmaf(r[j], dtw[j * kDI + d], acc);

    const float dtv = softplusf(acc);
    const float Ad  = -expf(A_log[d]);
    a[idx]  = expf(dtv * Ad);
    bu[idx] = dtv * r[kDTR] * u[idx];
}

// ---------------------------------------------------------------------------
// Selective scan (DS=1)
// ---------------------------------------------------------------------------
__global__ __launch_bounds__(256) void scan_kernel(
    const float* __restrict__ a, const float* __restrict__ bu,
    const float* __restrict__ u, const float* __restrict__ dtbc,
    const float* __restrict__ Dp, float* __restrict__ y)
{
    const int b = blockIdx.x / 3;
    const int d = (blockIdx.x % 3) * 256 + threadIdx.x;
    const float Dd = Dp[d];
    float h = 0.f;
    const size_t base = (size_t)b * kL * kDI + d;
    const size_t cbase = (size_t)b * kL;
#pragma unroll 4
    for (int l = 0; l < kL; l++) {
        const size_t idx = base + (size_t)l * kDI;
        const float cc = __ldg(&dtbc[(cbase + l) * kXPK + (kDTR + 1)]);
        h = fmaf(a[idx], h, bu[idx]);
        y[idx] = fmaf(h, cc, u[idx] * Dd);
    }
}

// ---------------------------------------------------------------------------
// Launch
// ---------------------------------------------------------------------------
extern "C" void kernel_launch(void* const* d_in, const int* in_sizes, int n_in,
                              void* d_out, int out_size)
{
    const float* x         = (const float*)d_in[0];
    const float* ln1_g     = (const float*)d_in[1];
    const float* ln1_b     = (const float*)d_in[2];
    const float* w_in      = (const float*)d_in[3];
    const float* conv_w    = (const float*)d_in[4];
    const float* x_proj_w  = (const float*)d_in[5];
    const float* dt_proj_w = (const float*)d_in[6];
    const float* dt_proj_b = (const float*)d_in[7];
    const float* A_log     = (const float*)d_in[8];
    const float* Dp        = (const float*)d_in[9];
    const float* outnorm_g = (const float*)d_in[10];
    const float* outnorm_b = (const float*)d_in[11];
    const float* w_out     = (const float*)d_in[12];
    const float* ln2_g     = (const float*)d_in[13];
    const float* ln2_b     = (const float*)d_in[14];
    const float* fc1_w     = (const float*)d_in[15];
    const float* fc1_b     = (const float*)d_in[16];
    const float* fc2_w     = (const float*)d_in[17];
    const float* fc2_b     = (const float*)d_in[18];
    float* out = (float*)d_out;

    float *h1, *xz, *u, *dtbc, *a, *bu, *y, *gate, *xres, *h2, *hid;
    float *wt_in, *wt_out, *wt_f1, *wt_f2;
    cudaGetSymbolAddress((void**)&h1,    g_h1);
    cudaGetSymbolAddress((void**)&xz,    g_xz);
    cudaGetSymbolAddress((void**)&u,     g_u);
    cudaGetSymbolAddress((void**)&dtbc,  g_dtbc);
    cudaGetSymbolAddress((void**)&a,     g_a);
    cudaGetSymbolAddress((void**)&bu,    g_bu);
    cudaGetSymbolAddress((void**)&y,     g_y);
    cudaGetSymbolAddress((void**)&gate,  g_gate);
    cudaGetSymbolAddress((void**)&xres,  g_xres);
    cudaGetSymbolAddress((void**)&h2,    g_h2);
    cudaGetSymbolAddress((void**)&hid,   g_hid);
    cudaGetSymbolAddress((void**)&wt_in, g_wt_in);
    cudaGetSymbolAddress((void**)&wt_out,g_wt_out);
    cudaGetSymbolAddress((void**)&wt_f1, g_wt_f1);
    cudaGetSymbolAddress((void**)&wt_f2, g_wt_f2);

    // dynamic smem: DEPTH * (BM + BN) * BKP floats = 4 * 256 * 20 * 4B = 80 KB
    const int SMEM = 4 * 256 * 20 * 4;
    cudaFuncSetAttribute(mma_gemm<0>, cudaFuncAttributeMaxDynamicSharedMemorySize, SMEM);
    cudaFuncSetAttribute(mma_gemm<1>, cudaFuncAttributeMaxDynamicSharedMemorySize, SMEM);
    cudaFuncSetAttribute(mma_gemm<2>, cudaFuncAttributeMaxDynamicSharedMemorySize, SMEM);
    cudaFuncSetAttribute(mma_gemm<3>, cudaFuncAttributeMaxDynamicSharedMemorySize, SMEM);

    // 0) transpose weights to [N,K]
    transpose_kernel<<<dim3(2 * kDI / 32, kC / 32),  dim3(32, 8)>>>(w_in,  wt_in,  kC,   2 * kDI);
    transpose_kernel<<<dim3(kC / 32,      kDI / 32), dim3(32, 8)>>>(w_out, wt_out, kDI,  kC);
    transpose_kernel<<<dim3(kHID / 32,    kC / 32),  dim3(32, 8)>>>(fc1_w, wt_f1,  kC,   kHID);
    transpose_kernel<<<dim3(kC / 32,      kHID / 32),dim3(32, 8)>>>(fc2_w, wt_f2,  kHID, kC);

    // 1) h1 = LN(x)
    ln_kernel<kC, 128, false><<<kNTOK, 128>>>(x, nullptr, 0, 0, ln1_g, ln1_b, h1, 1e-6f);

    // 2) xz = h1 @ w_in   (M=16384, N=1536, K=384)
    mma_gemm<0><<<dim3((2 * kDI) / 128, kNTOK / 128), 256, SMEM>>>(
        h1, wt_in, xz, kNTOK, 2 * kDI, kC, nullptr, nullptr);

    // 3) u = silu(dwconv3x3(xm))
    conv_silu_kernel<<<(kNTOK * kDI) / 256, 256>>>(xz, conv_w, u);

    // 4) dtbc = u @ x_proj_w
    xproj_kernel<<<kNTOK / 8, 256>>>(u, x_proj_w, dtbc);

    // 5) dt coefficients
    dt_kernel<<<(kNTOK * kDI) / 256, 256>>>(dtbc, dt_proj_w, dt_proj_b, A_log, u, a, bu);

    // 6) selective scan
    scan_kernel<<<kB * 3, 256>>>(a, bu, u, dtbc, Dp, y);

    // 7) gate = LN_out(y) * silu(z)
    ln_kernel<kDI, 256, true><<<kNTOK, 256>>>(y, xz, 2 * kDI, kDI,
                                              outnorm_g, outnorm_b, gate, 1e-5f);

    // 8) xres = gate @ w_out + x   (N=384, K=768)
    mma_gemm<1><<<dim3(kC / 128, kNTOK / 128), 256, SMEM>>>(
        gate, wt_out, xres, kNTOK, kC, kDI, nullptr, x);

    // 9) h2 = LN(xres)
    ln_kernel<kC, 128, false><<<kNTOK, 128>>>(xres, nullptr, 0, 0, ln2_g, ln2_b, h2, 1e-6f);

    // 10) hid = gelu(h2 @ fc1_w + fc1_b)   (N=1536, K=384)
    mma_gemm<2><<<dim3(kHID / 128, kNTOK / 128), 256, SMEM>>>(
        h2, wt_f1, hid, kNTOK, kHID, kC, fc1_b, nullptr);

    // 11) out = hid @ fc2_w + fc2_b + xres   (N=384, K=1536)
    mma_gemm<3><<<dim3(kC / 128, kNTOK / 128), 256, SMEM>>>(
        hid, wt_f2, out, kNTOK, kC, kHID, fc2_b, xres);
}

// round 7
// speedup vs baseline: 2.0351x; 1.0594x over previous
#include <cuda_runtime.h>
#include <math.h>
#include <stdint.h>

// ---------------------------------------------------------------------------
// Problem constants
// ---------------------------------------------------------------------------
constexpr int kB     = 16;
constexpr int kH     = 32;
constexpr int kW     = 32;
constexpr int kC     = 384;
constexpr int kDI    = 768;
constexpr int kDTR   = 24;
constexpr int kHID   = 1536;
constexpr int kL     = kH * kW;          // 1024
constexpr int kNTOK  = kB * kL;          // 16384
constexpr int kXPK   = kDTR + 2;         // 26

// ---------------------------------------------------------------------------
// Scratch
// ---------------------------------------------------------------------------
__device__ float g_h1  [(size_t)kNTOK * kC];
__device__ float g_xz  [(size_t)kNTOK * 2 * kDI];
__device__ float g_u   [(size_t)kNTOK * kDI];
__device__ float g_dtbc[(size_t)kNTOK * kXPK];
__device__ float g_a   [(size_t)kNTOK * kDI];
__device__ float g_bu  [(size_t)kNTOK * kDI];
__device__ float g_y   [(size_t)kNTOK * kDI];
__device__ float g_gate[(size_t)kNTOK * kDI];
__device__ float g_xres[(size_t)kNTOK * kC];
__device__ float g_h2  [(size_t)kNTOK * kC];
__device__ float g_hid [(size_t)kNTOK * kHID];
// transposed weights ([N,K], pre-rounded to tf32)
__device__ float g_wt_in [(size_t)(2 * kDI) * kC];
__device__ float g_wt_out[(size_t)kC * kDI];
__device__ float g_wt_f1 [(size_t)kHID * kC];
__device__ float g_wt_f2 [(size_t)kC * kHID];

// ---------------------------------------------------------------------------
// Math helpers
// ---------------------------------------------------------------------------
__device__ __forceinline__ float siluf(float x) { return x / (1.f + expf(-x)); }
__device__ __forceinline__ float softplusf(float x) {
    return fmaxf(x, 0.f) + log1pf(expf(-fabsf(x)));
}
__device__ __forceinline__ float gelu_tanh(float x) {
    float x3 = x * x * x;
    return 0.5f * x * (1.f + tanhf(0.7978845608028654f * (x + 0.044715f * x3)));
}

// ---------------------------------------------------------------------------
// PTX helpers (sm_80-safe: cp.async + mma.sync only)
// ---------------------------------------------------------------------------
__device__ __forceinline__ uint32_t smem_to_u32(const void* p) {
    uint32_t a;
    asm("{ .reg .u64 t; cvta.to.shared.u64 t, %1; cvt.u32.u64 %0, t; }" : "=r"(a) : "l"(p));
    return a;
}
__device__ __forceinline__ void cp_async16(uint32_t sa, const void* g) {
    asm volatile("cp.async.cg.shared.global [%0], [%1], 16;" :: "r"(sa), "l"(g));
}
__device__ __forceinline__ void cp_commit() { asm volatile("cp.async.commit_group;" ::: "memory"); }
template <int N>
__device__ __forceinline__ void cp_wait() { asm volatile("cp.async.wait_group %0;" :: "n"(N) : "memory"); }

__device__ __forceinline__ uint32_t to_tf32(float v) {
    uint32_t u;
    asm("cvt.rna.tf32.f32 %0, %1;" : "=r"(u) : "f"(v));
    return u;
}
__device__ __forceinline__ float round_tf32(float v) {
    return __uint_as_float(to_tf32(v));
}
__device__ __forceinline__ void mma_tf32(float* c, const uint32_t* a, const uint32_t* b) {
    asm volatile(
        "mma.sync.aligned.m16n8k8.row.col.f32.tf32.tf32.f32 "
        "{%0,%1,%2,%3}, {%4,%5,%6,%7}, {%8,%9}, {%0,%1,%2,%3};"
        : "+f"(c[0]), "+f"(c[1]), "+f"(c[2]), "+f"(c[3])
        : "r"(a[0]), "r"(a[1]), "r"(a[2]), "r"(a[3]), "r"(b[0]), "r"(b[1]));
}

// ---------------------------------------------------------------------------
// tf32 mma.sync GEMM: C[M,N] = A[M,K] @ Bt[N,K]^T  (+ fused epilogue)
//   Operands must be PRE-ROUNDED to tf32 (bit pattern) by their producers.
//   EPI: 0=store  1=+resid  2=+bias->gelu(round to tf32)  3=+bias+resid
//   BM=BN=128, BK=16, DEPTH=4 cp.async stages, 256 threads (8 warps, 2x4).
// ---------------------------------------------------------------------------
template <int EPI>
__global__ __launch_bounds__(256, 2) void mma_gemm(
    const float* __restrict__ A, const float* __restrict__ Bt,
    float* __restrict__ C, int M, int N, int K,
    const float* __restrict__ bias, const float* __restrict__ resid)
{
    constexpr int BM = 128, BN = 128, BK = 16, BKP = 20, DEPTH = 4;
    constexpr int A_ELEMS = BM * BKP;
    constexpr int B_ELEMS = BN * BKP;

    extern __shared__ float sm[];
    float* sA = sm;
    float* sB = sm + DEPTH * A_ELEMS;
    const uint32_t sAu = smem_to_u32(sA);
    const uint32_t sBu = smem_to_u32(sB);

    const int tid  = threadIdx.x;
    const int wid  = tid >> 5, lane = tid & 31;
    const int grp  = lane >> 2, tg = lane & 3;
    const int m_w  = (wid & 1) * 64;
    const int n_w  = (wid >> 1) * 32;
    const int tile_m = blockIdx.y * BM;
    const int tile_n = blockIdx.x * BN;

    const int nst = K / BK;
    const int ld_row = tid >> 2;
    const int ld_seg = tid & 3;

    auto load_stage = [&](int s) {
        const int slot = s % DEPTH;
        const int k0 = s * BK;
        const float* ap = A + (size_t)tile_m * K + k0;
        const uint32_t da = sAu + (uint32_t)(slot * A_ELEMS) * 4u;
#pragma unroll
        for (int p = 0; p < 2; p++) {
            const int row = ld_row + p * 64;
            cp_async16(da + (uint32_t)(row * BKP + ld_seg * 4) * 4u,
                       ap + (size_t)row * K + ld_seg * 4);
        }
        const float* bp = Bt + (size_t)tile_n * K + k0;
        const uint32_t db = sBu + (uint32_t)(slot * B_ELEMS) * 4u;
#pragma unroll
        for (int p = 0; p < 2; p++) {
            const int row = ld_row + p * 64;
            cp_async16(db + (uint32_t)(row * BKP + ld_seg * 4) * 4u,
                       bp + (size_t)row * K + ld_seg * 4);
        }
        cp_commit();
    };

    float acc[4][4][4];
#pragma unroll
    for (int i = 0; i < 4; i++)
#pragma unroll
        for (int j = 0; j < 4; j++)
#pragma unroll
            for (int r = 0; r < 4; r++) acc[i][j][r] = 0.f;

    const int pre = (nst < DEPTH - 1) ? nst : (DEPTH - 1);
    for (int s = 0; s < pre; s++) load_stage(s);

    for (int s = 0; s < nst; s++) {
        cp_wait<DEPTH - 2>();
        __syncthreads();

        const int nxt = s + DEPTH - 1;
        if (nxt < nst) load_stage(nxt);

        const int slot = s % DEPTH;
        const uint32_t* Ab = reinterpret_cast<const uint32_t*>(sA) +
                             slot * A_ELEMS + (m_w + grp) * BKP + tg;
        const uint32_t* Bb = reinterpret_cast<const uint32_t*>(sB) +
                             slot * B_ELEMS + (n_w + grp) * BKP + tg;

#pragma unroll
        for (int kk = 0; kk < 2; kk++) {
            const int k0 = kk * 8;
            uint32_t af[4][4];
#pragma unroll
            for (int i = 0; i < 4; i++) {
                const uint32_t* ar = Ab + i * 16 * BKP + k0;
                af[i][0] = ar[0];
                af[i][1] = ar[8 * BKP];
                af[i][2] = ar[4];
                af[i][3] = ar[8 * BKP + 4];
            }
            uint32_t bf[4][2];
#pragma unroll
            for (int j = 0; j < 4; j++) {
                const uint32_t* br = Bb + j * 8 * BKP + k0;
                bf[j][0] = br[0];
                bf[j][1] = br[4];
            }
#pragma unroll
            for (int i = 0; i < 4; i++)
#pragma unroll
                for (int j = 0; j < 4; j++)
                    mma_tf32(acc[i][j], af[i], bf[j]);
        }
        __syncthreads();
    }

    // ---- Epilogue ----
#pragma unroll
    for (int i = 0; i < 4; i++) {
        const int rg0 = tile_m + m_w + i * 16 + grp;
#pragma unroll
        for (int j = 0; j < 4; j++) {
            const int cg = tile_n + n_w + j * 8 + tg * 2;
#pragma unroll
            for (int h = 0; h < 2; h++) {
                const int rg = rg0 + h * 8;
                float2 v = make_float2(acc[i][j][h * 2], acc[i][j][h * 2 + 1]);
                const size_t off = (size_t)rg * N + cg;
                if (EPI == 1) {
                    float2 rr = *reinterpret_cast<const float2*>(resid + off);
                    v.x += rr.x; v.y += rr.y;
                }
                if (EPI == 2) {
                    float2 bb = *reinterpret_cast<const float2*>(bias + cg);
                    v.x = round_tf32(gelu_tanh(v.x + bb.x));   // feeds fc2 GEMM
                    v.y = round_tf32(gelu_tanh(v.y + bb.y));
                }
                if (EPI == 3) {
                    float2 bb = *reinterpret_cast<const float2*>(bias + cg);
                    float2 rr = *reinterpret_cast<const float2*>(resid + off);
                    v.x += bb.x + rr.x; v.y += bb.y + rr.y;
                }
                *reinterpret_cast<float2*>(C + off) = v;
            }
        }
    }
}

// ---------------------------------------------------------------------------
// 32x32 tiled transpose + tf32 rounding: out[N,K] = tf32(in[K,N]^T)
// ---------------------------------------------------------------------------
__global__ void transpose_kernel(const float* __restrict__ in,
                                 float* __restrict__ out, int K, int N)
{
    __shared__ float t[32][33];
    const int n0 = blockIdx.x * 32, k0 = blockIdx.y * 32;
    const int x = threadIdx.x, y = threadIdx.y;
#pragma unroll
    for (int i = y; i < 32; i += 8)
        t[i][x] = in[(size_t)(k0 + i) * N + n0 + x];
    __syncthreads();
#pragma unroll
    for (int i = y; i < 32; i += 8)
        out[(size_t)(n0 + i) * K + k0 + x] = round_tf32(t[x][i]);
}

// ---------------------------------------------------------------------------
// LayerNorm (optionally * silu(z); optionally round stores to tf32)
// ---------------------------------------------------------------------------
template <int CH, int TPB, bool MUL_SILU, bool RND>
__global__ __launch_bounds__(TPB) void ln_kernel(
    const float* __restrict__ in,
    const float* __restrict__ zsrc, int zld, int zoff,
    const float* __restrict__ gam, const float* __restrict__ bet,
    float* __restrict__ out, float eps)
{
    constexpr int PER = CH / TPB;
    const int n = blockIdx.x;
    const float* row = in + (size_t)n * CH;

    float v[PER];
    float s = 0.f, s2 = 0.f;
#pragma unroll
    for (int i = 0; i < PER; i++) {
        float t = row[i * TPB + threadIdx.x];
        v[i] = t; s += t; s2 += t * t;
    }
    __shared__ float sm[2 * (TPB / 32)];
#pragma unroll
    for (int o = 16; o; o >>= 1) {
        s  += __shfl_down_sync(0xffffffffu, s,  o);
        s2 += __shfl_down_sync(0xffffffffu, s2, o);
    }
    const int wid = threadIdx.x >> 5, lid = threadIdx.x & 31;
    if (lid == 0) { sm[wid] = s; sm[TPB / 32 + wid] = s2; }
    __syncthreads();
    if (threadIdx.x == 0) {
        float a = 0.f, b = 0.f;
#pragma unroll
        for (int i = 0; i < TPB / 32; i++) { a += sm[i]; b += sm[TPB / 32 + i]; }
        sm[0] = a; sm[1] = b;
    }
    __syncthreads();
    const float mu  = sm[0] * (1.f / CH);
    const float var = sm[1] * (1.f / CH) - mu * mu;
    const float inv = rsqrtf(var + eps);
#pragma unroll
    for (int i = 0; i < PER; i++) {
        const int c = i * TPB + threadIdx.x;
        float o = (v[i] - mu) * inv * gam[c] + bet[c];
        if (MUL_SILU) {
            float z = zsrc[(size_t)n * zld + zoff + c];
            o *= siluf(z);
        }
        if (RND) o = round_tf32(o);
        out[(size_t)n * CH + c] = o;
    }
}

// ---------------------------------------------------------------------------
// Depthwise 3x3 SAME conv + silu. float4 over channels; weights staged in
// smem transposed+vectorized: scwv[k][d4] (k in 0..8, d4 in 0..191).
// ---------------------------------------------------------------------------
__global__ __launch_bounds__(256) void conv_silu_kernel(
    const float* __restrict__ xz, const float* __restrict__ cw,
    float* __restrict__ u)
{
    constexpr int D4 = kDI / 4;   // 192
    __shared__ float4 scwv[9 * D4];
    for (int i = threadIdx.x; i < 9 * D4; i += 256) {
        const int k = i / D4, d4 = i % D4;
        scwv[i] = make_float4(cw[(d4 * 4 + 0) * 9 + k], cw[(d4 * 4 + 1) * 9 + k],
                              cw[(d4 * 4 + 2) * 9 + k], cw[(d4 * 4 + 3) * 9 + k]);
    }
    __syncthreads();

    const int idx = blockIdx.x * 256 + threadIdx.x;
    if (idx >= kNTOK * D4) return;
    const int d4 = idx % D4;
    const int n  = idx / D4;
    const int w  = n % kW;
    const int h  = (n / kW) % kH;

    float4 acc = make_float4(0.f, 0.f, 0.f, 0.f);
#pragma unroll
    for (int ky = 0; ky < 3; ky++) {
        const int hh = h + ky - 1;
        if (hh < 0 || hh >= kH) continue;
#pragma unroll
        for (int kx = 0; kx < 3; kx++) {
            const int ww = w + kx - 1;
            if (ww < 0 || ww >= kW) continue;
            const int nn = n + (ky - 1) * kW + (kx - 1);
            const float4 v = *reinterpret_cast<const float4*>(
                xz + (size_t)nn * (2 * kDI) + d4 * 4);
            const float4 wv = scwv[(ky * 3 + kx) * D4 + d4];
            acc.x = fmaf(wv.x, v.x, acc.x);
            acc.y = fmaf(wv.y, v.y, acc.y);
            acc.z = fmaf(wv.z, v.z, acc.z);
            acc.w = fmaf(wv.w, v.w, acc.w);
        }
    }
    float4 o = make_float4(siluf(acc.x), siluf(acc.y), siluf(acc.z), siluf(acc.w));
    *reinterpret_cast<float4*>(u + (size_t)n * kDI + d4 * 4) = o;
}

// ---------------------------------------------------------------------------
// x_proj (768 -> 26): 32 tokens per block, u tile staged in smem (no shfl).
// ---------------------------------------------------------------------------
__global__ __launch_bounds__(256) void xproj_kernel(
    const float* __restrict__ u, const float* __restrict__ W,
    float* __restrict__ out)
{
    __shared__ float sW[64 * kXPK];     // 64 x 26
    __shared__ float su[32][65];        // 32 tokens x 64 k-chunk (+pad)
    const int warp = threadIdx.x >> 5, lane = threadIdx.x & 31;
    const int nb = blockIdx.x * 32;
    float acc[4] = {0.f, 0.f, 0.f, 0.f};

    for (int j0 = 0; j0 < kDI; j0 += 64) {
        for (int i = threadIdx.x; i < 64 * kXPK; i += 256)
            sW[i] = W[j0 * kXPK + i];
        // stage u[nb..nb+32)[j0..j0+64)
        {
            const int col = threadIdx.x & 63;
            for (int r = threadIdx.x >> 6; r < 32; r += 4)
                su[r][col] = u[(size_t)(nb + r) * kDI + j0 + col];
        }
        __syncthreads();

#pragma unroll
        for (int t = 0; t < 4; t++) {
            const int tok = warp * 4 + t;
            if (lane < kXPK) {
#pragma unroll
                for (int jj = 0; jj < 64; jj++)
                    acc[t] = fmaf(su[tok][jj], sW[jj * kXPK + lane], acc[t]);
            }
        }
        __syncthreads();
    }
    if (lane < kXPK) {
#pragma unroll
        for (int t = 0; t < 4; t++)
            out[(size_t)(nb + warp * 4 + t) * kXPK + lane] = acc[t];
    }
}

// ---------------------------------------------------------------------------
// dt_proj + softplus + scan coefficients
// ---------------------------------------------------------------------------
__global__ void dt_kernel(const float* __restrict__ dtbc,
                          const float* __restrict__ dtw,
                          const float* __restrict__ dtb,
                          const float* __restrict__ A_log,
                          const float* __restrict__ u,
                          float* __restrict__ a, float* __restrict__ bu)
{
    const int idx = blockIdx.x * blockDim.x + threadIdx.x;
    if (idx >= kNTOK * kDI) return;
    const int d = idx % kDI;
    const int n = idx / kDI;
    const float* r = dtbc + (size_t)n * kXPK;

    float acc = dtb[d];
#pragma unroll
    for (int j = 0; j < kDTR; j++)
        acc = fmaf(r[j], dtw[j * kDI + d], acc);

    const float dtv = softplusf(acc);
    const float Ad  = -expf(A_log[d]);
    a[idx]  = expf(dtv * Ad);
    bu[idx] = dtv * r[kDTR] * u[idx];
}

// ---------------------------------------------------------------------------
// Selective scan (DS=1)
// ---------------------------------------------------------------------------
__global__ __launch_bounds__(256) void scan_kernel(
    const float* __restrict__ a, const float* __restrict__ bu,
    const float* __restrict__ u, const float* __restrict__ dtbc,
    const float* __restrict__ Dp, float* __restrict__ y)
{
    const int b = blockIdx.x / 3;
    const int d = (blockIdx.x % 3) * 256 + threadIdx.x;
    const float Dd = Dp[d];
    float h = 0.f;
    const size_t base = (size_t)b * kL * kDI + d;
    const size_t cbase = (size_t)b * kL;
#pragma unroll 4
    for (int l = 0; l < kL; l++) {
        const size_t idx = base + (size_t)l * kDI;
        const float cc = __ldg(&dtbc[(cbase + l) * kXPK + (kDTR + 1)]);
        h = fmaf(a[idx], h, bu[idx]);
        y[idx] = fmaf(h, cc, u[idx] * Dd);
    }
}

// ---------------------------------------------------------------------------
// Launch
// ---------------------------------------------------------------------------
extern "C" void kernel_launch(void* const* d_in, const int* in_sizes, int n_in,
                              void* d_out, int out_size)
{
    const float* x         = (const float*)d_in[0];
    const float* ln1_g     = (const float*)d_in[1];
    const float* ln1_b     = (const float*)d_in[2];
    const float* w_in      = (const float*)d_in[3];
    const float* conv_w    = (const float*)d_in[4];
    const float* x_proj_w  = (const float*)d_in[5];
    const float* dt_proj_w = (const float*)d_in[6];
    const float* dt_proj_b = (const float*)d_in[7];
    const float* A_log     = (const float*)d_in[8];
    const float* Dp        = (const float*)d_in[9];
    const float* outnorm_g = (const float*)d_in[10];
    const float* outnorm_b = (const float*)d_in[11];
    const float* w_out     = (const float*)d_in[12];
    const float* ln2_g     = (const float*)d_in[13];
    const float* ln2_b     = (const float*)d_in[14];
    const float* fc1_w     = (const float*)d_in[15];
    const float* fc1_b     = (const float*)d_in[16];
    const float* fc2_w     = (const float*)d_in[17];
    const float* fc2_b     = (const float*)d_in[18];
    float* out = (float*)d_out;

    float *h1, *xz, *u, *dtbc, *a, *bu, *y, *gate, *xres, *h2, *hid;
    float *wt_in, *wt_out, *wt_f1, *wt_f2;
    cudaGetSymbolAddress((void**)&h1,    g_h1);
    cudaGetSymbolAddress((void**)&xz,    g_xz);
    cudaGetSymbolAddress((void**)&u,     g_u);
    cudaGetSymbolAddress((void**)&dtbc,  g_dtbc);
    cudaGetSymbolAddress((void**)&a,     g_a);
    cudaGetSymbolAddress((void**)&bu,    g_bu);
    cudaGetSymbolAddress((void**)&y,     g_y);
    cudaGetSymbolAddress((void**)&gate,  g_gate);
    cudaGetSymbolAddress((void**)&xres,  g_xres);
    cudaGetSymbolAddress((void**)&h2,    g_h2);
    cudaGetSymbolAddress((void**)&hid,   g_hid);
    cudaGetSymbolAddress((void**)&wt_in, g_wt_in);
    cudaGetSymbolAddress((void**)&wt_out,g_wt_out);
    cudaGetSymbolAddress((void**)&wt_f1, g_wt_f1);
    cudaGetSymbolAddress((void**)&wt_f2, g_wt_f2);

    const int SMEM = 4 * 256 * 20 * 4;   // 80 KB
    cudaFuncSetAttribute(mma_gemm<0>, cudaFuncAttributeMaxDynamicSharedMemorySize, SMEM);
    cudaFuncSetAttribute(mma_gemm<1>, cudaFuncAttributeMaxDynamicSharedMemorySize, SMEM);
    cudaFuncSetAttribute(mma_gemm<2>, cudaFuncAttributeMaxDynamicSharedMemorySize, SMEM);
    cudaFuncSetAttribute(mma_gemm<3>, cudaFuncAttributeMaxDynamicSharedMemorySize, SMEM);

    // 0) transpose + tf32-round weights
    transpose_kernel<<<dim3(2 * kDI / 32, kC / 32),  dim3(32, 8)>>>(w_in,  wt_in,  kC,   2 * kDI);
    transpose_kernel<<<dim3(kC / 32,      kDI / 32), dim3(32, 8)>>>(w_out, wt_out, kDI,  kC);
    transpose_kernel<<<dim3(kHID / 32,    kC / 32),  dim3(32, 8)>>>(fc1_w, wt_f1,  kC,   kHID);
    transpose_kernel<<<dim3(kC / 32,      kHID / 32),dim3(32, 8)>>>(fc2_w, wt_f2,  kHID, kC);

    // 1) h1 = tf32(LN(x))  — GEMM-only consumer
    ln_kernel<kC, 128, false, true><<<kNTOK, 128>>>(x, nullptr, 0, 0, ln1_g, ln1_b, h1, 1e-6f);

    // 2) xz = h1 @ w_in
    mma_gemm<0><<<dim3((2 * kDI) / 128, kNTOK / 128), 256, SMEM>>>(
        h1, wt_in, xz, kNTOK, 2 * kDI, kC, nullptr, nullptr);

    // 3) u = silu(dwconv3x3(xm))
    conv_silu_kernel<<<(kNTOK * (kDI / 4) + 255) / 256, 256>>>(xz, conv_w, u);

    // 4) dtbc = u @ x_proj_w
    xproj_kernel<<<kNTOK / 32, 256>>>(u, x_proj_w, dtbc);

    // 5) dt coefficients
    dt_kernel<<<(kNTOK * kDI) / 256, 256>>>(dtbc, dt_proj_w, dt_proj_b, A_log, u, a, bu);

    // 6) selective scan
    scan_kernel<<<kB * 3, 256>>>(a, bu, u, dtbc, Dp, y);

    // 7) gate = tf32(LN_out(y) * silu(z))  — GEMM-only consumer
    ln_kernel<kDI, 256, true, true><<<kNTOK, 256>>>(y, xz, 2 * kDI, kDI,
                                                    outnorm_g, outnorm_b, gate, 1e-5f);

    // 8) xres = gate @ w_out + x
    mma_gemm<1><<<dim3(kC / 128, kNTOK / 128), 256, SMEM>>>(
        gate, wt_out, xres, kNTOK, kC, kDI, nullptr, x);

    // 9) h2 = tf32(LN(xres))  — GEMM-only consumer
    ln_kernel<kC, 128, false, true><<<kNTOK, 128>>>(xres, nullptr, 0, 0, ln2_g, ln2_b, h2, 1e-6f);

    // 10) hid = tf32(gelu(h2 @ fc1_w + fc1_b))  — feeds fc2 GEMM
    mma_gemm<2><<<dim3(kHID / 128, kNTOK / 128), 256, SMEM>>>(
        h2, wt_f1, hid, kNTOK, kHID, kC, fc1_b, nullptr);

    // 11) out = hid @ fc2_w + fc2_b + xres
    mma_gemm<3><<<dim3(kC / 128, kNTOK / 128), 256, SMEM>>>(
        hid, wt_f2, out, kNTOK, kC, kHID, fc2_b, xres);
}

// round 8
// speedup vs baseline: 2.2940x; 1.1272x over previous
#include <cuda_runtime.h>
#include <math.h>
#include <stdint.h>

// ---------------------------------------------------------------------------
// Problem constants
// ---------------------------------------------------------------------------
constexpr int kB     = 16;
constexpr int kH     = 32;
constexpr int kW     = 32;
constexpr int kC     = 384;
constexpr int kDI    = 768;
constexpr int kDTR   = 24;
constexpr int kHID   = 1536;
constexpr int kL     = kH * kW;          // 1024
constexpr int kNTOK  = kB * kL;          // 16384
constexpr int kXPK   = kDTR + 2;         // 26

// ---------------------------------------------------------------------------
// Scratch
// ---------------------------------------------------------------------------
__device__ float g_h1  [(size_t)kNTOK * kC];
__device__ float g_xz  [(size_t)kNTOK * 2 * kDI];
__device__ float g_u   [(size_t)kNTOK * kDI];
__device__ float g_dtbc[(size_t)kNTOK * kXPK];
__device__ float g_a   [(size_t)kNTOK * kDI];
__device__ float g_bu  [(size_t)kNTOK * kDI];
__device__ float g_y   [(size_t)kNTOK * kDI];
__device__ float g_gate[(size_t)kNTOK * kDI];
__device__ float g_xres[(size_t)kNTOK * kC];
__device__ float g_h2  [(size_t)kNTOK * kC];
__device__ float g_hid [(size_t)kNTOK * kHID];
// transposed weights ([N,K], pre-rounded to tf32)
__device__ float g_wt_in [(size_t)(2 * kDI) * kC];
__device__ float g_wt_out[(size_t)kC * kDI];
__device__ float g_wt_f1 [(size_t)kHID * kC];
__device__ float g_wt_f2 [(size_t)kC * kHID];

// ---------------------------------------------------------------------------
// Math helpers
// ---------------------------------------------------------------------------
__device__ __forceinline__ float siluf(float x) {
    return __fdividef(x, 1.f + __expf(-x));
}
__device__ __forceinline__ float gelu_tanh(float x) {
    float x3 = x * x * x;
    float targ = 0.7978845608028654f * (x + 0.044715f * x3);
    float th;
    asm("tanh.approx.f32 %0, %1;" : "=f"(th) : "f"(targ));
    return 0.5f * x * (1.f + th);
}

// ---------------------------------------------------------------------------
// PTX helpers (sm_80-safe: cp.async + mma.sync + ldmatrix)
// ---------------------------------------------------------------------------
__device__ __forceinline__ uint32_t smem_to_u32(const void* p) {
    uint32_t a;
    asm("{ .reg .u64 t; cvta.to.shared.u64 t, %1; cvt.u32.u64 %0, t; }" : "=r"(a) : "l"(p));
    return a;
}
__device__ __forceinline__ void cp_async16(uint32_t sa, const void* g) {
    asm volatile("cp.async.cg.shared.global [%0], [%1], 16;" :: "r"(sa), "l"(g));
}
__device__ __forceinline__ void cp_commit() { asm volatile("cp.async.commit_group;" ::: "memory"); }
template <int N>
__device__ __forceinline__ void cp_wait() { asm volatile("cp.async.wait_group %0;" :: "n"(N) : "memory"); }

__device__ __forceinline__ uint32_t to_tf32(float v) {
    uint32_t u;
    asm("cvt.rna.tf32.f32 %0, %1;" : "=r"(u) : "f"(v));
    return u;
}
__device__ __forceinline__ float round_tf32(float v) {
    return __uint_as_float(to_tf32(v));
}
__device__ __forceinline__ void ldsm_x4(uint32_t& r0, uint32_t& r1, uint32_t& r2,
                                        uint32_t& r3, uint32_t addr) {
    asm volatile("ldmatrix.sync.aligned.m8n8.x4.shared.b16 {%0,%1,%2,%3}, [%4];"
                 : "=r"(r0), "=r"(r1), "=r"(r2), "=r"(r3) : "r"(addr));
}
__device__ __forceinline__ void mma_tf32(float* c, const uint32_t* a, const uint32_t* b) {
    asm volatile(
        "mma.sync.aligned.m16n8k8.row.col.f32.tf32.tf32.f32 "
        "{%0,%1,%2,%3}, {%4,%5,%6,%7}, {%8,%9}, {%0,%1,%2,%3};"
        : "+f"(c[0]), "+f"(c[1]), "+f"(c[2]), "+f"(c[3])
        : "r"(a[0]), "r"(a[1]), "r"(a[2]), "r"(a[3]), "r"(b[0]), "r"(b[1]));
}

// ---------------------------------------------------------------------------
// tf32 mma.sync GEMM: C[M,N] = A[M,K] @ Bt[N,K]^T  (+ fused epilogue)
//   Operands pre-rounded to tf32 by producers. Fragments via ldmatrix.
//   EPI: 0=store  1=+resid  2=+bias->gelu(tf32)  3=+bias+resid
//   BM=BN=128, BK=16, BKP=20, DEPTH=4, 256 threads (8 warps, 2x4).
// ---------------------------------------------------------------------------
template <int EPI>
__global__ __launch_bounds__(256, 2) void mma_gemm(
    const float* __restrict__ A, const float* __restrict__ Bt,
    float* __restrict__ C, int M, int N, int K,
    const float* __restrict__ bias, const float* __restrict__ resid)
{
    constexpr int BM = 128, BN = 128, BK = 16, BKP = 20, DEPTH = 4;
    constexpr int A_ELEMS = BM * BKP;
    constexpr int B_ELEMS = BN * BKP;

    extern __shared__ float sm[];
    float* sA = sm;
    float* sB = sm + DEPTH * A_ELEMS;
    const uint32_t sAu = smem_to_u32(sA);
    const uint32_t sBu = smem_to_u32(sB);

    const int tid  = threadIdx.x;
    const int wid  = tid >> 5, lane = tid & 31;
    const int grp  = lane >> 2, tg = lane & 3;
    const int m_w  = (wid & 1) * 64;
    const int n_w  = (wid >> 1) * 32;
    const int tile_m = blockIdx.y * BM;
    const int tile_n = blockIdx.x * BN;

    const int nst = K / BK;
    const int ld_row = tid >> 2;
    const int ld_seg = tid & 3;

    // ldmatrix per-lane source offsets (bytes, within a stage slot)
    const int q  = lane >> 3;       // matrix index 0..3
    const int rr = lane & 7;        // row within 8
    // A x4 per (i,kk): m0 rows0-7 k0-3, m1 rows8-15 k0-3, m2 rows0-7 k4-7, m3 rows8-15 k4-7
    const uint32_t aoff = (uint32_t)(((m_w + (q & 1) * 8 + rr) * BKP + (q >> 1) * 4) * 4);
    // B x4 per (jg,kk): m0 j rows k0-3, m1 j rows k4-7, m2 j+1 rows k0-3, m3 j+1 rows k4-7
    const uint32_t boff = (uint32_t)(((n_w + (q >> 1) * 8 + rr) * BKP + (q & 1) * 4) * 4);

    auto load_stage = [&](int s) {
        const int slot = s % DEPTH;
        const int k0 = s * BK;
        const float* ap = A + (size_t)tile_m * K + k0;
        const uint32_t da = sAu + (uint32_t)(slot * A_ELEMS) * 4u;
#pragma unroll
        for (int p = 0; p < 2; p++) {
            const int row = ld_row + p * 64;
            cp_async16(da + (uint32_t)(row * BKP + ld_seg * 4) * 4u,
                       ap + (size_t)row * K + ld_seg * 4);
        }
        const float* bp = Bt + (size_t)tile_n * K + k0;
        const uint32_t db = sBu + (uint32_t)(slot * B_ELEMS) * 4u;
#pragma unroll
        for (int p = 0; p < 2; p++) {
            const int row = ld_row + p * 64;
            cp_async16(db + (uint32_t)(row * BKP + ld_seg * 4) * 4u,
                       bp + (size_t)row * K + ld_seg * 4);
        }
        cp_commit();
    };

    float acc[4][4][4];
#pragma unroll
    for (int i = 0; i < 4; i++)
#pragma unroll
        for (int j = 0; j < 4; j++)
#pragma unroll
            for (int r = 0; r < 4; r++) acc[i][j][r] = 0.f;

    const int pre = (nst < DEPTH - 1) ? nst : (DEPTH - 1);
    for (int s = 0; s < pre; s++) load_stage(s);

    for (int s = 0; s < nst; s++) {
        cp_wait<DEPTH - 2>();
        __syncthreads();   // all warps done reading stage s-1 -> safe to refill its slot

        const int nxt = s + DEPTH - 1;
        if (nxt < nst) load_stage(nxt);

        const int slot = s % DEPTH;
        const uint32_t aBase = sAu + (uint32_t)(slot * A_ELEMS) * 4u + aoff;
        const uint32_t bBase = sBu + (uint32_t)(slot * B_ELEMS) * 4u + boff;

#pragma unroll
        for (int kk = 0; kk < 2; kk++) {
            uint32_t af[4][4];
#pragma unroll
            for (int i = 0; i < 4; i++)
                ldsm_x4(af[i][0], af[i][1], af[i][2], af[i][3],
                        aBase + (uint32_t)((i * 16 * BKP + kk * 8) * 4));
            uint32_t bf[4][2];
            ldsm_x4(bf[0][0], bf[0][1], bf[1][0], bf[1][1],
                    bBase + (uint32_t)((kk * 8) * 4));
            ldsm_x4(bf[2][0], bf[2][1], bf[3][0], bf[3][1],
                    bBase + (uint32_t)((16 * BKP + kk * 8) * 4));
#pragma unroll
            for (int i = 0; i < 4; i++)
#pragma unroll
                for (int j = 0; j < 4; j++)
                    mma_tf32(acc[i][j], af[i], bf[j]);
        }
        // no trailing sync: 4-deep ring, next write targets slot of stage s-1,
        // whose reads are ordered by the sync at the top of the next iteration
    }

    // ---- Epilogue (registers + gmem only) ----
#pragma unroll
    for (int i = 0; i < 4; i++) {
        const int rg0 = tile_m + m_w + i * 16 + grp;
#pragma unroll
        for (int j = 0; j < 4; j++) {
            const int cg = tile_n + n_w + j * 8 + tg * 2;
#pragma unroll
            for (int h = 0; h < 2; h++) {
                const int rg = rg0 + h * 8;
                float2 v = make_float2(acc[i][j][h * 2], acc[i][j][h * 2 + 1]);
                const size_t off = (size_t)rg * N + cg;
                if (EPI == 1) {
                    float2 rr2 = *reinterpret_cast<const float2*>(resid + off);
                    v.x += rr2.x; v.y += rr2.y;
                }
                if (EPI == 2) {
                    float2 bb = *reinterpret_cast<const float2*>(bias + cg);
                    v.x = round_tf32(gelu_tanh(v.x + bb.x));
                    v.y = round_tf32(gelu_tanh(v.y + bb.y));
                }
                if (EPI == 3) {
                    float2 bb = *reinterpret_cast<const float2*>(bias + cg);
                    float2 rr2 = *reinterpret_cast<const float2*>(resid + off);
                    v.x += bb.x + rr2.x; v.y += bb.y + rr2.y;
                }
                *reinterpret_cast<float2*>(C + off) = v;
            }
        }
    }
}

// ---------------------------------------------------------------------------
// 32x32 tiled transpose + tf32 rounding: out[N,K] = tf32(in[K,N]^T)
// ---------------------------------------------------------------------------
__global__ void transpose_kernel(const float* __restrict__ in,
                                 float* __restrict__ out, int K, int N)
{
    __shared__ float t[32][33];
    const int n0 = blockIdx.x * 32, k0 = blockIdx.y * 32;
    const int x = threadIdx.x, y = threadIdx.y;
#pragma unroll
    for (int i = y; i < 32; i += 8)
        t[i][x] = in[(size_t)(k0 + i) * N + n0 + x];
    __syncthreads();
#pragma unroll
    for (int i = y; i < 32; i += 8)
        out[(size_t)(n0 + i) * K + k0 + x] = round_tf32(t[x][i]);
}

// ---------------------------------------------------------------------------
// LayerNorm (optionally * silu(z); optionally round stores to tf32)
// ---------------------------------------------------------------------------
template <int CH, int TPB, bool MUL_SILU, bool RND>
__global__ __launch_bounds__(TPB) void ln_kernel(
    const float* __restrict__ in,
    const float* __restrict__ zsrc, int zld, int zoff,
    const float* __restrict__ gam, const float* __restrict__ bet,
    float* __restrict__ out, float eps)
{
    constexpr int PER = CH / TPB;
    const int n = blockIdx.x;
    const float* row = in + (size_t)n * CH;

    float v[PER];
    float s = 0.f, s2 = 0.f;
#pragma unroll
    for (int i = 0; i < PER; i++) {
        float t = row[i * TPB + threadIdx.x];
        v[i] = t; s += t; s2 += t * t;
    }
    __shared__ float sm[2 * (TPB / 32)];
#pragma unroll
    for (int o = 16; o; o >>= 1) {
        s  += __shfl_down_sync(0xffffffffu, s,  o);
        s2 += __shfl_down_sync(0xffffffffu, s2, o);
    }
    const int wid = threadIdx.x >> 5, lid = threadIdx.x & 31;
    if (lid == 0) { sm[wid] = s; sm[TPB / 32 + wid] = s2; }
    __syncthreads();
    if (threadIdx.x == 0) {
        float a = 0.f, b = 0.f;
#pragma unroll
        for (int i = 0; i < TPB / 32; i++) { a += sm[i]; b += sm[TPB / 32 + i]; }
        sm[0] = a; sm[1] = b;
    }
    __syncthreads();
    const float mu  = sm[0] * (1.f / CH);
    const float var = sm[1] * (1.f / CH) - mu * mu;
    const float inv = rsqrtf(var + eps);
#pragma unroll
    for (int i = 0; i < PER; i++) {
        const int c = i * TPB + threadIdx.x;
        float o = (v[i] - mu) * inv * gam[c] + bet[c];
        if (MUL_SILU) {
            float z = zsrc[(size_t)n * zld + zoff + c];
            o *= siluf(z);
        }
        if (RND) o = round_tf32(o);
        out[(size_t)n * CH + c] = o;
    }
}

// ---------------------------------------------------------------------------
// Depthwise 3x3 SAME conv + silu (float4 channels, weights staged in smem)
// ---------------------------------------------------------------------------
__global__ __launch_bounds__(256) void conv_silu_kernel(
    const float* __restrict__ xz, const float* __restrict__ cw,
    float* __restrict__ u)
{
    constexpr int D4 = kDI / 4;   // 192
    __shared__ float4 scwv[9 * D4];
    for (int i = threadIdx.x; i < 9 * D4; i += 256) {
        const int k = i / D4, d4 = i % D4;
        scwv[i] = make_float4(cw[(d4 * 4 + 0) * 9 + k], cw[(d4 * 4 + 1) * 9 + k],
                              cw[(d4 * 4 + 2) * 9 + k], cw[(d4 * 4 + 3) * 9 + k]);
    }
    __syncthreads();

    const int idx = blockIdx.x * 256 + threadIdx.x;
    if (idx >= kNTOK * D4) return;
    const int d4 = idx % D4;
    const int n  = idx / D4;
    const int w  = n % kW;
    const int h  = (n / kW) % kH;

    float4 acc = make_float4(0.f, 0.f, 0.f, 0.f);
#pragma unroll
    for (int ky = 0; ky < 3; ky++) {
        const int hh = h + ky - 1;
        if (hh < 0 || hh >= kH) continue;
#pragma unroll
        for (int kx = 0; kx < 3; kx++) {
            const int ww = w + kx - 1;
            if (ww < 0 || ww >= kW) continue;
            const int nn = n + (ky - 1) * kW + (kx - 1);
            const float4 v = *reinterpret_cast<const float4*>(
                xz + (size_t)nn * (2 * kDI) + d4 * 4);
            const float4 wv = scwv[(ky * 3 + kx) * D4 + d4];
            acc.x = fmaf(wv.x, v.x, acc.x);
            acc.y = fmaf(wv.y, v.y, acc.y);
            acc.z = fmaf(wv.z, v.z, acc.z);
            acc.w = fmaf(wv.w, v.w, acc.w);
        }
    }
    float4 o = make_float4(siluf(acc.x), siluf(acc.y), siluf(acc.z), siluf(acc.w));
    *reinterpret_cast<float4*>(u + (size_t)n * kDI + d4 * 4) = o;
}

// ---------------------------------------------------------------------------
// x_proj (768 -> 26): 32 tokens per block, u tile staged in smem
// ---------------------------------------------------------------------------
__global__ __launch_bounds__(256) void xproj_kernel(
    const float* __restrict__ u, const float* __restrict__ W,
    float* __restrict__ out)
{
    __shared__ float sW[64 * kXPK];
    __shared__ float su[32][65];
    const int warp = threadIdx.x >> 5, lane = threadIdx.x & 31;
    const int nb = blockIdx.x * 32;
    float acc[4] = {0.f, 0.f, 0.f, 0.f};

    for (int j0 = 0; j0 < kDI; j0 += 64) {
        for (int i = threadIdx.x; i < 64 * kXPK; i += 256)
            sW[i] = W[j0 * kXPK + i];
        {
            const int col = threadIdx.x & 63;
            for (int r = threadIdx.x >> 6; r < 32; r += 4)
                su[r][col] = u[(size_t)(nb + r) * kDI + j0 + col];
        }
        __syncthreads();

#pragma unroll
        for (int t = 0; t < 4; t++) {
            const int tok = warp * 4 + t;
            if (lane < kXPK) {
#pragma unroll
                for (int jj = 0; jj < 64; jj++)
                    acc[t] = fmaf(su[tok][jj], sW[jj * kXPK + lane], acc[t]);
            }
        }
        __syncthreads();
    }
    if (lane < kXPK) {
#pragma unroll
        for (int t = 0; t < 4; t++)
            out[(size_t)(nb + warp * 4 + t) * kXPK + lane] = acc[t];
    }
}

// ---------------------------------------------------------------------------
// dt_proj + softplus + scan coefficients.
//   Per thread: one d-channel (weights in 24 regs), 64 tokens via smem tile.
//   a = exp(Ad*softplus(z)) = 2^(Ad * log2(1+2^(z*log2e)))  (3 MUFU)
// ---------------------------------------------------------------------------
constexpr int kDTTOK = 64;
__global__ __launch_bounds__(256) void dt_kernel(
    const float* __restrict__ dtbc, const float* __restrict__ dtw,
    const float* __restrict__ dtb,  const float* __restrict__ A_log,
    const float* __restrict__ u,
    float* __restrict__ a, float* __restrict__ bu)
{
    __shared__ float sdt[kDTTOK][kXPK];
    const int d  = blockIdx.y * 256 + threadIdx.x;
    const int nb = blockIdx.x * kDTTOK;

    float wreg[kDTR];
#pragma unroll
    for (int j = 0; j < kDTR; j++) wreg[j] = dtw[j * kDI + d];
    const float bias = dtb[d];
    const float Ad   = -__expf(A_log[d]);

    for (int i = threadIdx.x; i < kDTTOK * kXPK; i += 256)
        sdt[i / kXPK][i % kXPK] = dtbc[(size_t)nb * kXPK + i];
    __syncthreads();

    constexpr float L2E = 1.4426950408889634f;
    constexpr float LN2 = 0.6931471805599453f;
#pragma unroll 4
    for (int t = 0; t < kDTTOK; t++) {
        float z = bias;
#pragma unroll
        for (int j = 0; j < kDTR; j++) z = fmaf(sdt[t][j], wreg[j], z);

        float l;   // log2(1 + e^z)
        if (z > 15.f) l = z * L2E;
        else          l = __log2f(1.f + exp2f(z * L2E));
        const float dtv = l * LN2;

        const size_t idx = (size_t)(nb + t) * kDI + d;
        a[idx]  = exp2f(Ad * l);
        bu[idx] = dtv * sdt[t][kDTR] * u[idx];
    }
}

// ---------------------------------------------------------------------------
// Selective scan (DS=1)
// ---------------------------------------------------------------------------
__global__ __launch_bounds__(256) void scan_kernel(
    const float* __restrict__ a, const float* __restrict__ bu,
    const float* __restrict__ u, const float* __restrict__ dtbc,
    const float* __restrict__ Dp, float* __restrict__ y)
{
    const int b = blockIdx.x / 3;
    const int d = (blockIdx.x % 3) * 256 + threadIdx.x;
    const float Dd = Dp[d];
    float h = 0.f;
    const size_t base = (size_t)b * kL * kDI + d;
    const size_t cbase = (size_t)b * kL;
#pragma unroll 4
    for (int l = 0; l < kL; l++) {
        const size_t idx = base + (size_t)l * kDI;
        const float cc = __ldg(&dtbc[(cbase + l) * kXPK + (kDTR + 1)]);
        h = fmaf(a[idx], h, bu[idx]);
        y[idx] = fmaf(h, cc, u[idx] * Dd);
    }
}

// ---------------------------------------------------------------------------
// Launch
// ---------------------------------------------------------------------------
extern "C" void kernel_launch(void* const* d_in, const int* in_sizes, int n_in,
                              void* d_out, int out_size)
{
    const float* x         = (const float*)d_in[0];
    const float* ln1_g     = (const float*)d_in[1];
    const float* ln1_b     = (const float*)d_in[2];
    const float* w_in      = (const float*)d_in[3];
    const float* conv_w    = (const float*)d_in[4];
    const float* x_proj_w  = (const float*)d_in[5];
    const float* dt_proj_w = (const float*)d_in[6];
    const float* dt_proj_b = (const float*)d_in[7];
    const float* A_log     = (const float*)d_in[8];
    const float* Dp        = (const float*)d_in[9];
    const float* outnorm_g = (const float*)d_in[10];
    const float* outnorm_b = (const float*)d_in[11];
    const float* w_out     = (const float*)d_in[12];
    const float* ln2_g     = (const float*)d_in[13];
    const float* ln2_b     = (const float*)d_in[14];
    const float* fc1_w     = (const float*)d_in[15];
    const float* fc1_b     = (const float*)d_in[16];
    const float* fc2_w     = (const float*)d_in[17];
    const float* fc2_b     = (const float*)d_in[18];
    float* out = (float*)d_out;

    float *h1, *xz, *u, *dtbc, *a, *bu, *y, *gate, *xres, *h2, *hid;
    float *wt_in, *wt_out, *wt_f1, *wt_f2;
    cudaGetSymbolAddress((void**)&h1,    g_h1);
    cudaGetSymbolAddress((void**)&xz,    g_xz);
    cudaGetSymbolAddress((void**)&u,     g_u);
    cudaGetSymbolAddress((void**)&dtbc,  g_dtbc);
    cudaGetSymbolAddress((void**)&a,     g_a);
    cudaGetSymbolAddress((void**)&bu,    g_bu);
    cudaGetSymbolAddress((void**)&y,     g_y);
    cudaGetSymbolAddress((void**)&gate,  g_gate);
    cudaGetSymbolAddress((void**)&xres,  g_xres);
    cudaGetSymbolAddress((void**)&h2,    g_h2);
    cudaGetSymbolAddress((void**)&hid,   g_hid);
    cudaGetSymbolAddress((void**)&wt_in, g_wt_in);
    cudaGetSymbolAddress((void**)&wt_out,g_wt_out);
    cudaGetSymbolAddress((void**)&wt_f1, g_wt_f1);
    cudaGetSymbolAddress((void**)&wt_f2, g_wt_f2);

    const int SMEM = 4 * 256 * 20 * 4;   // 80 KB
    cudaFuncSetAttribute(mma_gemm<0>, cudaFuncAttributeMaxDynamicSharedMemorySize, SMEM);
    cudaFuncSetAttribute(mma_gemm<1>, cudaFuncAttributeMaxDynamicSharedMemorySize, SMEM);
    cudaFuncSetAttribute(mma_gemm<2>, cudaFuncAttributeMaxDynamicSharedMemorySize, SMEM);
    cudaFuncSetAttribute(mma_gemm<3>, cudaFuncAttributeMaxDynamicSharedMemorySize, SMEM);

    // 0) transpose + tf32-round weights
    transpose_kernel<<<dim3(2 * kDI / 32, kC / 32),  dim3(32, 8)>>>(w_in,  wt_in,  kC,   2 * kDI);
    transpose_kernel<<<dim3(kC / 32,      kDI / 32), dim3(32, 8)>>>(w_out, wt_out, kDI,  kC);
    transpose_kernel<<<dim3(kHID / 32,    kC / 32),  dim3(32, 8)>>>(fc1_w, wt_f1,  kC,   kHID);
    transpose_kernel<<<dim3(kC / 32,      kHID / 32),dim3(32, 8)>>>(fc2_w, wt_f2,  kHID, kC);

    // 1) h1 = tf32(LN(x))
    ln_kernel<kC, 128, false, true><<<kNTOK, 128>>>(x, nullptr, 0, 0, ln1_g, ln1_b, h1, 1e-6f);

    // 2) xz = h1 @ w_in
    mma_gemm<0><<<dim3((2 * kDI) / 128, kNTOK / 128), 256, SMEM>>>(
        h1, wt_in, xz, kNTOK, 2 * kDI, kC, nullptr, nullptr);

    // 3) u = silu(dwconv3x3(xm))
    conv_silu_kernel<<<(kNTOK * (kDI / 4) + 255) / 256, 256>>>(xz, conv_w, u);

    // 4) dtbc = u @ x_proj_w
    xproj_kernel<<<kNTOK / 32, 256>>>(u, x_proj_w, dtbc);

    // 5) dt coefficients
    dt_kernel<<<dim3(kNTOK / kDTTOK, kDI / 256), 256>>>(
        dtbc, dt_proj_w, dt_proj_b, A_log, u, a, bu);

    // 6) selective scan
    scan_kernel<<<kB * 3, 256>>>(a, bu, u, dtbc, Dp, y);

    // 7) gate = tf32(LN_out(y) * silu(z))
    ln_kernel<kDI, 256, true, true><<<kNTOK, 256>>>(y, xz, 2 * kDI, kDI,
                                                    outnorm_g, outnorm_b, gate, 1e-5f);

    // 8) xres = gate @ w_out + x
    mma_gemm<1><<<dim3(kC / 128, kNTOK / 128), 256, SMEM>>>(
        gate, wt_out, xres, kNTOK, kC, kDI, nullptr, x);

    // 9) h2 = tf32(LN(xres))
    ln_kernel<kC, 128, false, true><<<kNTOK, 128>>>(xres, nullptr, 0, 0, ln2_g, ln2_b, h2, 1e-6f);

    // 10) hid = tf32(gelu(h2 @ fc1_w + fc1_b))
    mma_gemm<2><<<dim3(kHID / 128, kNTOK / 128), 256, SMEM>>>(
        h2, wt_f1, hid, kNTOK, kHID, kC, fc1_b, nullptr);

    // 11) out = hid @ fc2_w + fc2_b + xres
    mma_gemm<3><<<dim3(kC / 128, kNTOK / 128), 256, SMEM>>>(
        hid, wt_f2, out, kNTOK, kC, kHID, fc2_b, xres);
}

// round 9
// speedup vs baseline: 2.5544x; 1.1135x over previous
#include <cuda_runtime.h>
#include <math.h>
#include <stdint.h>

// ---------------------------------------------------------------------------
// Problem constants
// ---------------------------------------------------------------------------
constexpr int kB     = 16;
constexpr int kH     = 32;
constexpr int kW     = 32;
constexpr int kC     = 384;
constexpr int kDI    = 768;
constexpr int kDTR   = 24;
constexpr int kHID   = 1536;
constexpr int kL     = kH * kW;          // 1024
constexpr int kNTOK  = kB * kL;          // 16384
constexpr int kXPK   = kDTR + 2;         // 26
constexpr int kCH    = 128;              // scan chunk length
constexpr int kNCH   = kL / kCH;         // 8 chunks per sequence

// ---------------------------------------------------------------------------
// Scratch
// ---------------------------------------------------------------------------
__device__ float g_h1  [(size_t)kNTOK * kC];
__device__ float g_xz  [(size_t)kNTOK * 2 * kDI];
__device__ float g_u   [(size_t)kNTOK * kDI];
__device__ float g_dtbc[(size_t)kNTOK * kXPK];
__device__ float g_y   [(size_t)kNTOK * kDI];
__device__ float g_gate[(size_t)kNTOK * kDI];
__device__ float g_xres[(size_t)kNTOK * kC];
__device__ float g_h2  [(size_t)kNTOK * kC];
__device__ float g_hid [(size_t)kNTOK * kHID];
// chunked-scan state
__device__ float g_P  [(size_t)kB * kNCH * kDI];
__device__ float g_Q  [(size_t)kB * kNCH * kDI];
__device__ float g_h0 [(size_t)kB * kNCH * kDI];
// transposed weights ([N,K], pre-rounded to tf32)
__device__ float g_wt_in [(size_t)(2 * kDI) * kC];
__device__ float g_wt_out[(size_t)kC * kDI];
__device__ float g_wt_f1 [(size_t)kHID * kC];
__device__ float g_wt_f2 [(size_t)kC * kHID];

// ---------------------------------------------------------------------------
// Math helpers
// ---------------------------------------------------------------------------
__device__ __forceinline__ float siluf(float x) {
    return __fdividef(x, 1.f + __expf(-x));
}
__device__ __forceinline__ float gelu_tanh(float x) {
    float x3 = x * x * x;
    float targ = 0.7978845608028654f * (x + 0.044715f * x3);
    float th;
    asm("tanh.approx.f32 %0, %1;" : "=f"(th) : "f"(targ));
    return 0.5f * x * (1.f + th);
}

// ---------------------------------------------------------------------------
// PTX helpers (sm_80-safe: cp.async + mma.sync + ldmatrix)
// ---------------------------------------------------------------------------
__device__ __forceinline__ uint32_t smem_to_u32(const void* p) {
    uint32_t a;
    asm("{ .reg .u64 t; cvta.to.shared.u64 t, %1; cvt.u32.u64 %0, t; }" : "=r"(a) : "l"(p));
    return a;
}
__device__ __forceinline__ void cp_async16(uint32_t sa, const void* g) {
    asm volatile("cp.async.cg.shared.global [%0], [%1], 16;" :: "r"(sa), "l"(g));
}
__device__ __forceinline__ void cp_commit() { asm volatile("cp.async.commit_group;" ::: "memory"); }
template <int N>
__device__ __forceinline__ void cp_wait() { asm volatile("cp.async.wait_group %0;" :: "n"(N) : "memory"); }

__device__ __forceinline__ uint32_t to_tf32(float v) {
    uint32_t u;
    asm("cvt.rna.tf32.f32 %0, %1;" : "=r"(u) : "f"(v));
    return u;
}
__device__ __forceinline__ float round_tf32(float v) {
    return __uint_as_float(to_tf32(v));
}
__device__ __forceinline__ void ldsm_x4(uint32_t& r0, uint32_t& r1, uint32_t& r2,
                                        uint32_t& r3, uint32_t addr) {
    asm volatile("ldmatrix.sync.aligned.m8n8.x4.shared.b16 {%0,%1,%2,%3}, [%4];"
                 : "=r"(r0), "=r"(r1), "=r"(r2), "=r"(r3) : "r"(addr));
}
__device__ __forceinline__ void mma_tf32(float* c, const uint32_t* a, const uint32_t* b) {
    asm volatile(
        "mma.sync.aligned.m16n8k8.row.col.f32.tf32.tf32.f32 "
        "{%0,%1,%2,%3}, {%4,%5,%6,%7}, {%8,%9}, {%0,%1,%2,%3};"
        : "+f"(c[0]), "+f"(c[1]), "+f"(c[2]), "+f"(c[3])
        : "r"(a[0]), "r"(a[1]), "r"(a[2]), "r"(a[3]), "r"(b[0]), "r"(b[1]));
}

// ---------------------------------------------------------------------------
// tf32 mma.sync GEMM: C[M,N] = A[M,K] @ Bt[N,K]^T  (+ fused epilogue)
//   Operands pre-rounded to tf32. Fragments via ldmatrix.
//   EPI: 0=store  1=+resid  2=+bias->gelu(tf32)  3=+bias+resid
//   BM=BN=128, BK=32, BKP=36, DEPTH=3, 256 threads (8 warps, 2x4).
// ---------------------------------------------------------------------------
template <int EPI>
__global__ __launch_bounds__(256, 2) void mma_gemm(
    const float* __restrict__ A, const float* __restrict__ Bt,
    float* __restrict__ C, int M, int N, int K,
    const float* __restrict__ bias, const float* __restrict__ resid)
{
    constexpr int BM = 128, BN = 128, BK = 32, BKP = 36, DEPTH = 3;
    constexpr int A_ELEMS = BM * BKP;
    constexpr int B_ELEMS = BN * BKP;

    extern __shared__ float sm[];
    float* sA = sm;
    float* sB = sm + DEPTH * A_ELEMS;
    const uint32_t sAu = smem_to_u32(sA);
    const uint32_t sBu = smem_to_u32(sB);

    const int tid  = threadIdx.x;
    const int wid  = tid >> 5, lane = tid & 31;
    const int grp  = lane >> 2, tg = lane & 3;
    const int m_w  = (wid & 1) * 64;
    const int n_w  = (wid >> 1) * 32;
    const int tile_m = blockIdx.y * BM;
    const int tile_n = blockIdx.x * BN;

    const int nst = K / BK;
    const int ld_row = tid >> 1;              // 0..127
    const int ld_sb  = (tid & 1) * 4;         // segment base: 0 or 4

    // ldmatrix per-lane source offsets (bytes, within a stage slot)
    const int q  = lane >> 3;
    const int rr = lane & 7;
    const uint32_t aoff = (uint32_t)(((m_w + (q & 1) * 8 + rr) * BKP + (q >> 1) * 4) * 4);
    const uint32_t boff = (uint32_t)(((n_w + (q >> 1) * 8 + rr) * BKP + (q & 1) * 4) * 4);

    auto load_stage = [&](int s) {
        const int slot = s % DEPTH;
        const int k0 = s * BK;
        const float* ap = A + (size_t)(tile_m + ld_row) * K + k0;
        const uint32_t da = sAu + (uint32_t)(slot * A_ELEMS + ld_row * BKP) * 4u;
#pragma unroll
        for (int p = 0; p < 4; p++) {
            const int seg = ld_sb + p;
            cp_async16(da + (uint32_t)(seg * 16), ap + seg * 4);
        }
        const float* bp = Bt + (size_t)(tile_n + ld_row) * K + k0;
        const uint32_t db = sBu + (uint32_t)(slot * B_ELEMS + ld_row * BKP) * 4u;
#pragma unroll
        for (int p = 0; p < 4; p++) {
            const int seg = ld_sb + p;
            cp_async16(db + (uint32_t)(seg * 16), bp + seg * 4);
        }
        cp_commit();
    };

    float acc[4][4][4];
#pragma unroll
    for (int i = 0; i < 4; i++)
#pragma unroll
        for (int j = 0; j < 4; j++)
#pragma unroll
            for (int r = 0; r < 4; r++) acc[i][j][r] = 0.f;

    const int pre = (nst < DEPTH - 1) ? nst : (DEPTH - 1);
    for (int s = 0; s < pre; s++) load_stage(s);

    for (int s = 0; s < nst; s++) {
        if (s + DEPTH - 1 < nst) cp_wait<DEPTH - 2>();
        else                     cp_wait<0>();
        __syncthreads();

        const int nxt = s + DEPTH - 1;
        if (nxt < nst) load_stage(nxt);

        const int slot = s % DEPTH;
        const uint32_t aBase = sAu + (uint32_t)(slot * A_ELEMS) * 4u + aoff;
        const uint32_t bBase = sBu + (uint32_t)(slot * B_ELEMS) * 4u + boff;

#pragma unroll
        for (int kk = 0; kk < 4; kk++) {
            uint32_t af[4][4];
#pragma unroll
            for (int i = 0; i < 4; i++)
                ldsm_x4(af[i][0], af[i][1], af[i][2], af[i][3],
                        aBase + (uint32_t)((i * 16 * BKP + kk * 8) * 4));
            uint32_t bf[4][2];
            ldsm_x4(bf[0][0], bf[0][1], bf[1][0], bf[1][1],
                    bBase + (uint32_t)((kk * 8) * 4));
            ldsm_x4(bf[2][0], bf[2][1], bf[3][0], bf[3][1],
                    bBase + (uint32_t)((16 * BKP + kk * 8) * 4));
#pragma unroll
            for (int i = 0; i < 4; i++)
#pragma unroll
                for (int j = 0; j < 4; j++)
                    mma_tf32(acc[i][j], af[i], bf[j]);
        }
    }

    // ---- Epilogue ----
#pragma unroll
    for (int i = 0; i < 4; i++) {
        const int rg0 = tile_m + m_w + i * 16 + grp;
#pragma unroll
        for (int j = 0; j < 4; j++) {
            const int cg = tile_n + n_w + j * 8 + tg * 2;
#pragma unroll
            for (int h = 0; h < 2; h++) {
                const int rg = rg0 + h * 8;
                float2 v = make_float2(acc[i][j][h * 2], acc[i][j][h * 2 + 1]);
                const size_t off = (size_t)rg * N + cg;
                if (EPI == 1) {
                    float2 rr2 = *reinterpret_cast<const float2*>(resid + off);
                    v.x += rr2.x; v.y += rr2.y;
                }
                if (EPI == 2) {
                    float2 bb = *reinterpret_cast<const float2*>(bias + cg);
                    v.x = round_tf32(gelu_tanh(v.x + bb.x));
                    v.y = round_tf32(gelu_tanh(v.y + bb.y));
                }
                if (EPI == 3) {
                    float2 bb = *reinterpret_cast<const float2*>(bias + cg);
                    float2 rr2 = *reinterpret_cast<const float2*>(resid + off);
                    v.x += bb.x + rr2.x; v.y += bb.y + rr2.y;
                }
                *reinterpret_cast<float2*>(C + off) = v;
            }
        }
    }
}

// ---------------------------------------------------------------------------
// Fused transpose of all 4 weight matrices (+ tf32 rounding)
//   tile counts: w_in 576, w_out 288, fc1 576, fc2 576  -> 2016 blocks
// ---------------------------------------------------------------------------
__global__ void transpose_all_kernel(
    const float* __restrict__ w_in, const float* __restrict__ w_out,
    const float* __restrict__ fc1,  const float* __restrict__ fc2,
    float* __restrict__ o_in, float* __restrict__ o_out,
    float* __restrict__ o_f1, float* __restrict__ o_f2)
{
    __shared__ float t[32][33];
    const int bid = blockIdx.x;
    const float* in; float* out; int K, N, tix;
    if (bid < 576)       { in = w_in;  out = o_in;  K = kC;   N = 2 * kDI; tix = bid; }
    else if (bid < 864)  { in = w_out; out = o_out; K = kDI;  N = kC;      tix = bid - 576; }
    else if (bid < 1440) { in = fc1;   out = o_f1;  K = kC;   N = kHID;    tix = bid - 864; }
    else                 { in = fc2;   out = o_f2;  K = kHID; N = kC;      tix = bid - 1440; }
    const int ntx = N / 32;
    const int n0 = (tix % ntx) * 32, k0 = (tix / ntx) * 32;
    const int x = threadIdx.x, y = threadIdx.y;
#pragma unroll
    for (int i = y; i < 32; i += 8)
        t[i][x] = in[(size_t)(k0 + i) * N + n0 + x];
    __syncthreads();
#pragma unroll
    for (int i = y; i < 32; i += 8)
        out[(size_t)(n0 + i) * K + k0 + x] = round_tf32(t[x][i]);
}

// ---------------------------------------------------------------------------
// LayerNorm (optionally * silu(z); optionally round stores to tf32)
// ---------------------------------------------------------------------------
template <int CH, int TPB, bool MUL_SILU, bool RND>
__global__ __launch_bounds__(TPB) void ln_kernel(
    const float* __restrict__ in,
    const float* __restrict__ zsrc, int zld, int zoff,
    const float* __restrict__ gam, const float* __restrict__ bet,
    float* __restrict__ out, float eps)
{
    constexpr int PER = CH / TPB;
    const int n = blockIdx.x;
    const float* row = in + (size_t)n * CH;

    float v[PER];
    float s = 0.f, s2 = 0.f;
#pragma unroll
    for (int i = 0; i < PER; i++) {
        float t = row[i * TPB + threadIdx.x];
        v[i] = t; s += t; s2 += t * t;
    }
    __shared__ float sm[2 * (TPB / 32)];
#pragma unroll
    for (int o = 16; o; o >>= 1) {
        s  += __shfl_down_sync(0xffffffffu, s,  o);
        s2 += __shfl_down_sync(0xffffffffu, s2, o);
    }
    const int wid = threadIdx.x >> 5, lid = threadIdx.x & 31;
    if (lid == 0) { sm[wid] = s; sm[TPB / 32 + wid] = s2; }
    __syncthreads();
    if (threadIdx.x == 0) {
        float a = 0.f, b = 0.f;
#pragma unroll
        for (int i = 0; i < TPB / 32; i++) { a += sm[i]; b += sm[TPB / 32 + i]; }
        sm[0] = a; sm[1] = b;
    }
    __syncthreads();
    const float mu  = sm[0] * (1.f / CH);
    const float var = sm[1] * (1.f / CH) - mu * mu;
    const float inv = rsqrtf(var + eps);
#pragma unroll
    for (int i = 0; i < PER; i++) {
        const int c = i * TPB + threadIdx.x;
        float o = (v[i] - mu) * inv * gam[c] + bet[c];
        if (MUL_SILU) {
            float z = zsrc[(size_t)n * zld + zoff + c];
            o *= siluf(z);
        }
        if (RND) o = round_tf32(o);
        out[(size_t)n * CH + c] = o;
    }
}

// ---------------------------------------------------------------------------
// Depthwise 3x3 SAME conv + silu (float4 channels, weights staged in smem)
// ---------------------------------------------------------------------------
__global__ __launch_bounds__(256) void conv_silu_kernel(
    const float* __restrict__ xz, const float* __restrict__ cw,
    float* __restrict__ u)
{
    constexpr int D4 = kDI / 4;   // 192
    __shared__ float4 scwv[9 * D4];
    for (int i = threadIdx.x; i < 9 * D4; i += 256) {
        const int k = i / D4, d4 = i % D4;
        scwv[i] = make_float4(cw[(d4 * 4 + 0) * 9 + k], cw[(d4 * 4 + 1) * 9 + k],
                              cw[(d4 * 4 + 2) * 9 + k], cw[(d4 * 4 + 3) * 9 + k]);
    }
    __syncthreads();

    const int idx = blockIdx.x * 256 + threadIdx.x;
    if (idx >= kNTOK * D4) return;
    const int d4 = idx % D4;
    const int n  = idx / D4;
    const int w  = n % kW;
    const int h  = (n / kW) % kH;

    float4 acc = make_float4(0.f, 0.f, 0.f, 0.f);
#pragma unroll
    for (int ky = 0; ky < 3; ky++) {
        const int hh = h + ky - 1;
        if (hh < 0 || hh >= kH) continue;
#pragma unroll
        for (int kx = 0; kx < 3; kx++) {
            const int ww = w + kx - 1;
            if (ww < 0 || ww >= kW) continue;
            const int nn = n + (ky - 1) * kW + (kx - 1);
            const float4 v = *reinterpret_cast<const float4*>(
                xz + (size_t)nn * (2 * kDI) + d4 * 4);
            const float4 wv = scwv[(ky * 3 + kx) * D4 + d4];
            acc.x = fmaf(wv.x, v.x, acc.x);
            acc.y = fmaf(wv.y, v.y, acc.y);
            acc.z = fmaf(wv.z, v.z, acc.z);
            acc.w = fmaf(wv.w, v.w, acc.w);
        }
    }
    float4 o = make_float4(siluf(acc.x), siluf(acc.y), siluf(acc.z), siluf(acc.w));
    *reinterpret_cast<float4*>(u + (size_t)n * kDI + d4 * 4) = o;
}

// ---------------------------------------------------------------------------
// x_proj (768 -> 26): 32 tokens per block, u tile staged in smem
// ---------------------------------------------------------------------------
__global__ __launch_bounds__(256) void xproj_kernel(
    const float* __restrict__ u, const float* __restrict__ W,
    float* __restrict__ out)
{
    __shared__ float sW[64 * kXPK];
    __shared__ float su[32][65];
    const int warp = threadIdx.x >> 5, lane = threadIdx.x & 31;
    const int nb = blockIdx.x * 32;
    float acc[4] = {0.f, 0.f, 0.f, 0.f};

    for (int j0 = 0; j0 < kDI; j0 += 64) {
        for (int i = threadIdx.x; i < 64 * kXPK; i += 256)
            sW[i] = W[j0 * kXPK + i];
        {
            const int col = threadIdx.x & 63;
            for (int r = threadIdx.x >> 6; r < 32; r += 4)
                su[r][col] = u[(size_t)(nb + r) * kDI + j0 + col];
        }
        __syncthreads();

#pragma unroll
        for (int t = 0; t < 4; t++) {
            const int tok = warp * 4 + t;
            if (lane < kXPK) {
#pragma unroll
                for (int jj = 0; jj < 64; jj++)
                    acc[t] = fmaf(su[tok][jj], sW[jj * kXPK + lane], acc[t]);
            }
        }
        __syncthreads();
    }
    if (lane < kXPK) {
#pragma unroll
        for (int t = 0; t < 4; t++)
            out[(size_t)(nb + warp * 4 + t) * kXPK + lane] = acc[t];
    }
}

// ---------------------------------------------------------------------------
// Chunked selective scan with fused dt_proj (3 passes, DS=1)
//   dt math: l = log2(1+2^(z*log2e)); dt = l*ln2; a = 2^(Ad*l)
// ---------------------------------------------------------------------------
__device__ __forceinline__ void dt_math(float z, float Ad, float& av, float& dtv) {
    constexpr float L2E = 1.4426950408889634f;
    constexpr float LN2 = 0.6931471805599453f;
    float l;
    if (z > 15.f) l = z * L2E;
    else          l = __log2f(1.f + exp2f(z * L2E));
    dtv = l * LN2;
    av  = exp2f(Ad * l);
}

// Pass 1: per-(b,chunk,d): P = prod(a), Q = chunk scan from h=0
__global__ __launch_bounds__(256) void scan_chunk_kernel(
    const float* __restrict__ dtbc, const float* __restrict__ dtw,
    const float* __restrict__ dtb,  const float* __restrict__ A_log,
    const float* __restrict__ u,
    float* __restrict__ Pp, float* __restrict__ Qq)
{
    __shared__ float sdt[kCH][kXPK];
    const int d = blockIdx.y * 256 + threadIdx.x;
    const int b = blockIdx.x >> 3;
    const int c = blockIdx.x & 7;
    const size_t tokbase = (size_t)b * kL + c * kCH;

    float wreg[kDTR];
#pragma unroll
    for (int j = 0; j < kDTR; j++) wreg[j] = dtw[j * kDI + d];
    const float bias = dtb[d];
    const float Ad   = -__expf(A_log[d]);

    for (int i = threadIdx.x; i < kCH * kXPK; i += 256)
        sdt[i / kXPK][i % kXPK] = dtbc[tokbase * kXPK + i];
    __syncthreads();

    float P = 1.f, Q = 0.f;
#pragma unroll 4
    for (int t = 0; t < kCH; t++) {
        float z = bias;
#pragma unroll
        for (int j = 0; j < kDTR; j++) z = fmaf(sdt[t][j], wreg[j], z);
        float av, dtv;
        dt_math(z, Ad, av, dtv);
        const float buv = dtv * sdt[t][kDTR] * u[(tokbase + t) * kDI + d];
        P *= av;
        Q = fmaf(av, Q, buv);
    }
    const size_t o = (size_t)blockIdx.x * kDI + d;
    Pp[o] = P;
    Qq[o] = Q;
}

// Pass 2: serial prefix over the 8 chunk summaries -> h0 per (b,c,d)
__global__ __launch_bounds__(256) void scan_prefix_kernel(
    const float* __restrict__ Pp, const float* __restrict__ Qq,
    float* __restrict__ h0)
{
    const int idx = blockIdx.x * 256 + threadIdx.x;   // b*kDI + d
    const int b = idx / kDI, d = idx % kDI;
    float h = 0.f;
#pragma unroll
    for (int c = 0; c < kNCH; c++) {
        const size_t o = (size_t)(b * kNCH + c) * kDI + d;
        h0[o] = h;
        h = fmaf(Pp[o], h, Qq[o]);
    }
}

// Pass 3: recompute a,bu within chunk starting at h0, emit y
__global__ __launch_bounds__(256) void scan_apply_kernel(
    const float* __restrict__ dtbc, const float* __restrict__ dtw,
    const float* __restrict__ dtb,  const float* __restrict__ A_log,
    const float* __restrict__ u,    const float* __restrict__ Dp,
    const float* __restrict__ h0,   float* __restrict__ y)
{
    __shared__ float sdt[kCH][kXPK];
    const int d = blockIdx.y * 256 + threadIdx.x;
    const int b = blockIdx.x >> 3;
    const int c = blockIdx.x & 7;
    const size_t tokbase = (size_t)b * kL + c * kCH;

    float wreg[kDTR];
#pragma unroll
    for (int j = 0; j < kDTR; j++) wreg[j] = dtw[j * kDI + d];
    const float bias = dtb[d];
    const float Ad   = -__expf(A_log[d]);
    const float Dd   = Dp[d];

    for (int i = threadIdx.x; i < kCH * kXPK; i += 256)
        sdt[i / kXPK][i % kXPK] = dtbc[tokbase * kXPK + i];
    __syncthreads();

    float h = h0[(size_t)blockIdx.x * kDI + d];
#pragma unroll 4
    for (int t = 0; t < kCH; t++) {
        float z = bias;
#pragma unroll
        for (int j = 0; j < kDTR; j++) z = fmaf(sdt[t][j], wreg[j], z);
        float av, dtv;
        dt_math(z, Ad, av, dtv);
        const size_t idx = (tokbase + t) * kDI + d;
        const float uv = u[idx];
        h = fmaf(av, h, dtv * sdt[t][kDTR] * uv);
        y[idx] = fmaf(h, sdt[t][kDTR + 1], uv * Dd);
    }
}

// ---------------------------------------------------------------------------
// Launch
// ---------------------------------------------------------------------------
extern "C" void kernel_launch(void* const* d_in, const int* in_sizes, int n_in,
                              void* d_out, int out_size)
{
    const float* x         = (const float*)d_in[0];
    const float* ln1_g     = (const float*)d_in[1];
    const float* ln1_b     = (const float*)d_in[2];
    const float* w_in      = (const float*)d_in[3];
    const float* conv_w    = (const float*)d_in[4];
    const float* x_proj_w  = (const float*)d_in[5];
    const float* dt_proj_w = (const float*)d_in[6];
    const float* dt_proj_b = (const float*)d_in[7];
    const float* A_log     = (const float*)d_in[8];
    const float* Dp        = (const float*)d_in[9];
    const float* outnorm_g = (const float*)d_in[10];
    const float* outnorm_b = (const float*)d_in[11];
    const float* w_out     = (const float*)d_in[12];
    const float* ln2_g     = (const float*)d_in[13];
    const float* ln2_b     = (const float*)d_in[14];
    const float* fc1_w     = (const float*)d_in[15];
    const float* fc1_b     = (const float*)d_in[16];
    const float* fc2_w     = (const float*)d_in[17];
    const float* fc2_b     = (const float*)d_in[18];
    float* out = (float*)d_out;

    float *h1, *xz, *u, *dtbc, *y, *gate, *xres, *h2, *hid;
    float *Pp, *Qq, *h0;
    float *wt_in, *wt_out, *wt_f1, *wt_f2;
    cudaGetSymbolAddress((void**)&h1,    g_h1);
    cudaGetSymbolAddress((void**)&xz,    g_xz);
    cudaGetSymbolAddress((void**)&u,     g_u);
    cudaGetSymbolAddress((void**)&dtbc,  g_dtbc);
    cudaGetSymbolAddress((void**)&y,     g_y);
    cudaGetSymbolAddress((void**)&gate,  g_gate);
    cudaGetSymbolAddress((void**)&xres,  g_xres);
    cudaGetSymbolAddress((void**)&h2,    g_h2);
    cudaGetSymbolAddress((void**)&hid,   g_hid);
    cudaGetSymbolAddress((void**)&Pp,    g_P);
    cudaGetSymbolAddress((void**)&Qq,    g_Q);
    cudaGetSymbolAddress((void**)&h0,    g_h0);
    cudaGetSymbolAddress((void**)&wt_in, g_wt_in);
    cudaGetSymbolAddress((void**)&wt_out,g_wt_out);
    cudaGetSymbolAddress((void**)&wt_f1, g_wt_f1);
    cudaGetSymbolAddress((void**)&wt_f2, g_wt_f2);

    // dynamic smem: DEPTH(3) * (BM+BN)(256 rows) * BKP(36) * 4B = 110592
    const int SMEM = 3 * 256 * 36 * 4;
    cudaFuncSetAttribute(mma_gemm<0>, cudaFuncAttributeMaxDynamicSharedMemorySize, SMEM);
    cudaFuncSetAttribute(mma_gemm<1>, cudaFuncAttributeMaxDynamicSharedMemorySize, SMEM);
    cudaFuncSetAttribute(mma_gemm<2>, cudaFuncAttributeMaxDynamicSharedMemorySize, SMEM);
    cudaFuncSetAttribute(mma_gemm<3>, cudaFuncAttributeMaxDynamicSharedMemorySize, SMEM);

    // 0) transpose + tf32-round all weights (one launch)
    transpose_all_kernel<<<2016, dim3(32, 8)>>>(w_in, w_out, fc1_w, fc2_w,
                                                wt_in, wt_out, wt_f1, wt_f2);

    // 1) h1 = tf32(LN(x))
    ln_kernel<kC, 128, false, true><<<kNTOK, 128>>>(x, nullptr, 0, 0, ln1_g, ln1_b, h1, 1e-6f);

    // 2) xz = h1 @ w_in
    mma_gemm<0><<<dim3((2 * kDI) / 128, kNTOK / 128), 256, SMEM>>>(
        h1, wt_in, xz, kNTOK, 2 * kDI, kC, nullptr, nullptr);

    // 3) u = silu(dwconv3x3(xm))
    conv_silu_kernel<<<(kNTOK * (kDI / 4) + 255) / 256, 256>>>(xz, conv_w, u);

    // 4) dtbc = u @ x_proj_w
    xproj_kernel<<<kNTOK / 32, 256>>>(u, x_proj_w, dtbc);

    // 5) chunked selective scan with fused dt_proj
    scan_chunk_kernel<<<dim3(kB * kNCH, kDI / 256), 256>>>(
        dtbc, dt_proj_w, dt_proj_b, A_log, u, Pp, Qq);
    scan_prefix_kernel<<<(kB * kDI) / 256, 256>>>(Pp, Qq, h0);
    scan_apply_kernel<<<dim3(kB * kNCH, kDI / 256), 256>>>(
        dtbc, dt_proj_w, dt_proj_b, A_log, u, Dp, h0, y);

    // 6) gate = tf32(LN_out(y) * silu(z))
    ln_kernel<kDI, 256, true, true><<<kNTOK, 256>>>(y, xz, 2 * kDI, kDI,
                                                    outnorm_g, outnorm_b, gate, 1e-5f);

    // 7) xres = gate @ w_out + x
    mma_gemm<1><<<dim3(kC / 128, kNTOK / 128), 256, SMEM>>>(
        gate, wt_out, xres, kNTOK, kC, kDI, nullptr, x);

    // 8) h2 = tf32(LN(xres))
    ln_kernel<kC, 128, false, true><<<kNTOK, 128>>>(xres, nullptr, 0, 0, ln2_g, ln2_b, h2, 1e-6f);

    // 9) hid = tf32(gelu(h2 @ fc1_w + fc1_b))
    mma_gemm<2><<<dim3(kHID / 128, kNTOK / 128), 256, SMEM>>>(
        h2, wt_f1, hid, kNTOK, kHID, kC, fc1_b, nullptr);

    // 10) out = hid @ fc2_w + fc2_b + xres
    mma_gemm<3><<<dim3(kC / 128, kNTOK / 128), 256, SMEM>>>(
        hid, wt_f2, out, kNTOK, kC, kHID, fc2_b, xres);
}